// round 12
// baseline (speedup 1.0000x reference)
#include <cuda_runtime.h>
#include <cstdint>

#define H 1024
#define T 1024
#define NE 16
#define IT 512
#define IV 256

// ---------------- scratch ----------------
__device__ float d_G[T * H];        // shared gate raw -> silu'd in place
__device__ float d_U[T * H];        // shared up raw
__device__ float d_eg[2 * T * IT];  // expert gate raw (stride IT)
__device__ float d_eu[2 * T * IT];  // expert up raw
__device__ float d_act[2 * T * IT]; // silu(eg)*eu
__device__ float d_yp[2 * T * H];   // per-pair expert outputs
__device__ int   d_pairs[2][NE][T];
__device__ int   d_cnt[2][NE];
__device__ float d_wts[T][2];
__device__ int   d_sel[T][2];
__device__ int   d_modal[T];

// ---------------- helpers ----------------
__device__ __forceinline__ uint32_t f2tf(float f) {
    uint32_t r;
    asm("cvt.rna.tf32.f32 %0, %1;" : "=r"(r) : "f"(f));
    return r;
}
__device__ __forceinline__ int swz(int r) { return (r + (r >> 2)) & 3; }

__device__ __forceinline__ void mma_tf32(float* c, const uint32_t* a, uint32_t b0, uint32_t b1) {
    asm volatile(
        "mma.sync.aligned.m16n8k8.row.col.f32.tf32.tf32.f32 "
        "{%0,%1,%2,%3}, {%4,%5,%6,%7}, {%8,%9}, {%0,%1,%2,%3};"
        : "+f"(c[0]), "+f"(c[1]), "+f"(c[2]), "+f"(c[3])
        : "r"(a[0]), "r"(a[1]), "r"(a[2]), "r"(a[3]), "r"(b0), "r"(b1));
}

// ---------------- router ----------------
__global__ __launch_bounds__(256) void k_router(
    const float* __restrict__ x, const int* __restrict__ tt,
    const float* __restrict__ Wt, const float* __restrict__ bt,
    const float* __restrict__ Wv, const float* __restrict__ bv,
    float* __restrict__ logits_out)
{
    int lane = threadIdx.x & 31;
    int t = blockIdx.x * 8 + (threadIdx.x >> 5);
    if (t >= T) return;

    int mod = (tt[t] != 0) ? 1 : 0;
    const float* W = mod ? Wv : Wt;
    const float* bias = mod ? bv : bt;

    float4 xr[8];
#pragma unroll
    for (int j = 0; j < 8; ++j)
        xr[j] = *(const float4*)&x[(size_t)t * H + (lane + 32 * j) * 4];

    float logit[NE];
#pragma unroll
    for (int e = 0; e < NE; ++e) {
        const float* w = W + (size_t)e * H;
        float s = 0.f;
#pragma unroll
        for (int j = 0; j < 8; ++j) {
            float4 wv4 = *(const float4*)&w[(lane + 32 * j) * 4];
            s = fmaf(xr[j].x, wv4.x, s);
            s = fmaf(xr[j].y, wv4.y, s);
            s = fmaf(xr[j].z, wv4.z, s);
            s = fmaf(xr[j].w, wv4.w, s);
        }
#pragma unroll
        for (int o = 16; o; o >>= 1) s += __shfl_xor_sync(0xffffffffu, s, o);
        logit[e] = s;
    }

    float mx = logit[0];
#pragma unroll
    for (int e = 1; e < NE; ++e) mx = fmaxf(mx, logit[e]);
    float p[NE], sum = 0.f;
#pragma unroll
    for (int e = 0; e < NE; ++e) { p[e] = expf(logit[e] - mx); sum += p[e]; }
    float inv = 1.f / sum;
#pragma unroll
    for (int e = 0; e < NE; ++e) p[e] *= inv;

    int i0 = 0; float b0 = -1e30f;
#pragma unroll
    for (int e = 0; e < NE; ++e) { float sc = p[e] + bias[e]; if (sc > b0) { b0 = sc; i0 = e; } }
    int i1 = 0; float b1 = -1e30f;
#pragma unroll
    for (int e = 0; e < NE; ++e) {
        if (e == i0) continue;
        float sc = p[e] + bias[e];
        if (sc > b1) { b1 = sc; i1 = e; }
    }
    float w0 = p[i0], w1 = p[i1];
    float s2 = fmaxf(w0 + w1, 1e-12f);
    w0 /= s2; w1 /= s2;

    if (lane < NE) logits_out[(size_t)t * NE + lane] = logit[lane];
    if (lane == 0) {
        d_sel[t][0] = i0; d_sel[t][1] = i1;
        d_wts[t][0] = w0; d_wts[t][1] = w1;
        d_modal[t] = mod;
    }
}

// ---------------- deterministic list build ----------------
__global__ __launch_bounds__(1024) void k_build() {
    int w = threadIdx.x >> 5, lane = threadIdx.x & 31;
    int mod = w >> 4, e = w & 15;
    int cnt = 0;
    for (int base = 0; base < T; base += 32) {
        int t = base + lane;
        int match = 0, slot = 0;
        if (d_modal[t] == mod) {
            if (d_sel[t][0] == e) { match = 1; slot = 0; }
            else if (d_sel[t][1] == e) { match = 1; slot = 1; }
        }
        unsigned m = __ballot_sync(0xffffffffu, match);
        if (match) {
            int pos = cnt + __popc(m & ((1u << lane) - 1u));
            d_pairs[mod][e][pos] = (t << 1) | slot;
        }
        cnt += __popc(m);
    }
    if (lane == 0) d_cnt[mod][e] = cnt;
}

// ============ tf32 GEMM core: 64(M) x 128(N) block, warp tile 32x64 ============
// Conflict-free STS.128/LDS.128; k-interleaved mma feeding.
// TWO-DEEP register prefetch: LDG(t+2) issued at iter t, STS(t+1) at iter end
// -> each load gets ~2 compute periods before being awaited (covers DRAM lat).
// gmode: 0 direct rows; 1 A row = pair>>1, C row = pair; 2 A row = C row = pair
__device__ __forceinline__ void gemm_core(
    int gmode,
    const float* __restrict__ A, int lda,
    const float* __restrict__ B, int ldb,
    float* __restrict__ C, int ldc,
    int K, int mbase, int nbase,
    const int* __restrict__ plist, int cnt)
{
    __shared__ uint32_t As[2][64][16];
    __shared__ uint32_t Bs[2][128][16];
    __shared__ int rowid[64];

    const int tid = threadIdx.x;
    const int lane = tid & 31;
    const int warp = tid >> 5;
    const int wm = warp & 1, wn = warp >> 1;
    const int g = lane >> 2, tg = lane & 3;

    if (gmode != 0) {
        if (tid < 64) {
            int m = mbase + tid;
            rowid[tid] = (m < cnt) ? plist[m] : -1;
        }
        __syncthreads();
    }

    // ---- A pointers: f = tid + 128j -> m = f>>2, kq = f&3 ----
    const float* aptr[2];
    int am[2], akq[2];
#pragma unroll
    for (int j = 0; j < 2; ++j) {
        int f = tid + 128 * j;
        int m = f >> 2;
        int kq = f & 3;
        am[j] = m; akq[j] = kq;
        int r;
        if (gmode == 0) r = mbase + m;
        else {
            int pv = rowid[m];
            if (pv < 0) pv = 0;
            r = (gmode == 1) ? (pv >> 1) : pv;
        }
        aptr[j] = A + (size_t)r * lda + kq * 4;
    }

    // ---- B pointer: warp supplies k-quad kqB = warp; lane -> n ----
    const int kqB = warp;
    const int nl = lane;
    const float* bptr = B + (size_t)(4 * kqB) * ldb + nbase + nl;
    const size_t ldb1 = ldb, ldb2 = 2 * (size_t)ldb, ldb3 = 3 * (size_t)ldb;

    float acc[2][8][4];
#pragma unroll
    for (int a = 0; a < 2; ++a)
#pragma unroll
        for (int b = 0; b < 8; ++b)
#pragma unroll
            for (int c = 0; c < 4; ++c) acc[a][b][c] = 0.f;

    // two prefetch register sets (tile t lives in set t&1)
    float4 ar[2][2];
    float bv[2][4][4];

    auto LDG = [&](int s) {
#pragma unroll
        for (int j = 0; j < 2; ++j) ar[s][j] = *(const float4*)(aptr[j]);
#pragma unroll
        for (int grp = 0; grp < 4; ++grp) {
            bv[s][grp][0] = bptr[grp * 32];
            bv[s][grp][1] = bptr[ldb1 + grp * 32];
            bv[s][grp][2] = bptr[ldb2 + grp * 32];
            bv[s][grp][3] = bptr[ldb3 + grp * 32];
        }
        aptr[0] += 16; aptr[1] += 16;
        bptr += 16 * ldb1;
    };
    auto STS = [&](int s, int buf) {
#pragma unroll
        for (int j = 0; j < 2; ++j) {
            int m = am[j];
            uint4 w;
            w.x = f2tf(ar[s][j].x); w.y = f2tf(ar[s][j].y);
            w.z = f2tf(ar[s][j].z); w.w = f2tf(ar[s][j].w);
            *(uint4*)&As[buf][m][(akq[j] ^ swz(m)) << 2] = w;
        }
#pragma unroll
        for (int grp = 0; grp < 4; ++grp) {
            int n = nl + 32 * grp;
            uint4 w;
            w.x = f2tf(bv[s][grp][0]); w.y = f2tf(bv[s][grp][1]);
            w.z = f2tf(bv[s][grp][2]); w.w = f2tf(bv[s][grp][3]);
            *(uint4*)&Bs[buf][n][(kqB ^ swz(n)) << 2] = w;
        }
    };
    auto COMPUTE = [&](int buf) {
        uint32_t Af[2][2][4];
#pragma unroll
        for (int fm = 0; fm < 2; ++fm)
#pragma unroll
            for (int rr = 0; rr < 2; ++rr) {
                int m = wm * 32 + fm * 16 + g + rr * 8;
                uint4 v = *(const uint4*)&As[buf][m][(tg ^ swz(m)) << 2];
                Af[fm][rr][0] = v.x; Af[fm][rr][1] = v.y;
                Af[fm][rr][2] = v.z; Af[fm][rr][3] = v.w;
            }
#pragma unroll
        for (int half = 0; half < 2; ++half) {
            uint32_t Bf[4][4];
#pragma unroll
            for (int f4 = 0; f4 < 4; ++f4) {
                int fn = half * 4 + f4;
                int n = wn * 64 + fn * 8 + g;
                uint4 v = *(const uint4*)&Bs[buf][n][(tg ^ swz(n)) << 2];
                Bf[f4][0] = v.x; Bf[f4][1] = v.y; Bf[f4][2] = v.z; Bf[f4][3] = v.w;
            }
#pragma unroll
            for (int kk = 0; kk < 2; ++kk) {
                uint32_t a[2][4];
#pragma unroll
                for (int fm = 0; fm < 2; ++fm) {
                    a[fm][0] = Af[fm][0][2 * kk];
                    a[fm][1] = Af[fm][1][2 * kk];
                    a[fm][2] = Af[fm][0][2 * kk + 1];
                    a[fm][3] = Af[fm][1][2 * kk + 1];
                }
#pragma unroll
                for (int f4 = 0; f4 < 4; ++f4) {
                    int fn = half * 4 + f4;
                    uint32_t b0 = Bf[f4][2 * kk], b1 = Bf[f4][2 * kk + 1];
                    mma_tf32(acc[0][fn], a[0], b0, b1);
                    mma_tf32(acc[1][fn], a[1], b0, b1);
                }
            }
        }
    };

    int nk = K >> 4;     // all K here are >= 256, so nk >= 16
    LDG(0);              // tile 0 -> set 0
    LDG(1);              // tile 1 -> set 1
    STS(0, 0);           // tile 0 -> buf 0
    __syncthreads();
    for (int kt = 0; kt < nk; ++kt) {
        int cur = kt & 1;
        if (kt + 2 < nk) LDG(kt & 1);            // tile kt+2 -> set (kt+2)&1
        COMPUTE(cur);
        if (kt + 1 < nk) STS((kt + 1) & 1, cur ^ 1);
        __syncthreads();
    }

    // ---- epilogue ----
#pragma unroll
    for (int fm = 0; fm < 2; ++fm) {
#pragma unroll
        for (int h = 0; h < 2; ++h) {
            int ml = wm * 32 + fm * 16 + g + h * 8;
            int crow;
            bool valid = true;
            if (gmode != 0) {
                int pv = rowid[ml];
                valid = (pv >= 0);
                crow = pv;
            } else crow = mbase + ml;
            if (!valid) continue;
#pragma unroll
            for (int fn = 0; fn < 8; ++fn) {
                int nc = nbase + wn * 64 + fn * 8 + 2 * tg;
                *(float2*)&C[(size_t)crow * ldc + nc] =
                    make_float2(acc[fm][fn][2 * h], acc[fm][fn][2 * h + 1]);
            }
        }
    }
}

// ---------------- GEMM pass 1 ----------------
// z: 0 = shared gate, 1 = shared up, 2..33 = expert gate, 34..65 = expert up
__global__ __launch_bounds__(128, 3) void k_gemm1(
    const float* __restrict__ x, const float* __restrict__ sg, const float* __restrict__ su,
    const float* __restrict__ tgu, const float* __restrict__ vgu)
{
    int z = blockIdx.z;
    int mbase = blockIdx.x * 64;
    int nbase = blockIdx.y * 128;
    if (z < 2) {
        const float* Bm = z ? su : sg;
        float* Cm = z ? d_U : d_G;
        gemm_core(0, x, H, Bm, H, Cm, H, H, mbase, nbase, nullptr, 0);
        return;
    }
    int isup = (z >= 34);
    int idx = z - (isup ? 34 : 2);
    int mod = idx >> 4, e = idx & 15;
    int cnt = d_cnt[mod][e];
    if (mbase >= cnt) return;
    int I = mod ? IV : IT;
    if (nbase >= I) return;
    const float* gup = (mod ? vgu : tgu) + (size_t)e * H * 2 * I + (isup ? I : 0);
    float* Cm = isup ? d_eu : d_eg;
    gemm_core(1, x, H, gup, 2 * I, Cm, IT, H,
              mbase, nbase, &d_pairs[mod][e][0], cnt);
}

// ---------------- elementwise silu-mul ----------------
__global__ __launch_bounds__(256) void k_silu() {
    int gid = blockIdx.x * blockDim.x + threadIdx.x;  // float4 units, 524288 total
    const int NG = (T * H) / 4;                       // 262144
    float4 gv, uv;
    float4* outp;
    if (gid < NG) {
        gv = ((const float4*)d_G)[gid];
        uv = ((const float4*)d_U)[gid];
        outp = &((float4*)d_G)[gid];
    } else {
        int p = gid - NG;
        gv = ((const float4*)d_eg)[p];
        uv = ((const float4*)d_eu)[p];
        outp = &((float4*)d_act)[p];
    }
    float4 o;
    o.x = (gv.x / (1.f + __expf(-gv.x))) * uv.x;
    o.y = (gv.y / (1.f + __expf(-gv.y))) * uv.y;
    o.z = (gv.z / (1.f + __expf(-gv.z))) * uv.z;
    o.w = (gv.w / (1.f + __expf(-gv.w))) * uv.w;
    *outp = o;
}

// ---------------- GEMM pass 2 ----------------
// z: 0 = shared2 (G @ sd -> out), 1..32 = expert down
__global__ __launch_bounds__(128, 3) void k_gemm2(
    const float* __restrict__ sd, const float* __restrict__ tdn, const float* __restrict__ vdn,
    float* __restrict__ out)
{
    int z = blockIdx.z;
    int mbase = blockIdx.x * 64;
    int nbase = blockIdx.y * 128;
    if (z == 0) {
        gemm_core(0, d_G, H, sd, H, out, H, H, mbase, nbase, nullptr, 0);
        return;
    }
    int idx = z - 1;
    int mod = idx >> 4, e = idx & 15;
    int cnt = d_cnt[mod][e];
    if (mbase >= cnt) return;
    int I = mod ? IV : IT;
    const float* dn = (mod ? vdn : tdn) + (size_t)e * I * H;
    gemm_core(2, d_act, IT, dn, H, d_yp, H, I,
              mbase, nbase, &d_pairs[mod][e][0], cnt);
}

// ---------------- final combine ----------------
__global__ __launch_bounds__(256) void k_combine(float* __restrict__ out) {
    int gid = blockIdx.x * blockDim.x + threadIdx.x;   // float4 units
    int t = gid >> 8;
    int c4 = gid & 255;
    float w0 = d_wts[t][0], w1 = d_wts[t][1];
    float4 o = ((float4*)out)[gid];
    float4 a = ((const float4*)&d_yp[(size_t)(2 * t) * H])[c4];
    float4 b = ((const float4*)&d_yp[(size_t)(2 * t + 1) * H])[c4];
    o.x += w0 * a.x + w1 * b.x;
    o.y += w0 * a.y + w1 * b.y;
    o.z += w0 * a.z + w1 * b.z;
    o.w += w0 * a.w + w1 * b.w;
    ((float4*)out)[gid] = o;
}

// ---------------- launch ----------------
extern "C" void kernel_launch(void* const* d_in, const int* in_sizes, int n_in,
                              void* d_out, int out_size)
{
    const float* x   = (const float*)d_in[0];
    const int*   tt  = (const int*)d_in[1];
    const float* trw = (const float*)d_in[2];
    const float* tb  = (const float*)d_in[3];
    const float* tgu = (const float*)d_in[4];
    const float* tdn = (const float*)d_in[5];
    const float* vrw = (const float*)d_in[6];
    const float* vb  = (const float*)d_in[7];
    const float* vgu = (const float*)d_in[8];
    const float* vdn = (const float*)d_in[9];
    const float* sg  = (const float*)d_in[10];
    const float* su  = (const float*)d_in[11];
    const float* sd  = (const float*)d_in[12];

    float* out = (float*)d_out;
    float* logits = out + (size_t)T * H;

    k_router<<<128, 256>>>(x, tt, trw, tb, vrw, vb, logits);
    k_build<<<1, 1024>>>();
    k_gemm1<<<dim3(16, 8, 66), 128>>>(x, sg, su, tgu, vgu);
    k_silu<<<2048, 256>>>();
    k_gemm2<<<dim3(16, 8, 33), 128>>>(sd, tdn, vdn, out);
    k_combine<<<1024, 256>>>(out);
}

// round 13
// speedup vs baseline: 1.2053x; 1.2053x over previous
#include <cuda_runtime.h>
#include <cstdint>

#define H 1024
#define T 1024
#define NE 16
#define IT 512
#define IV 256

// ---------------- scratch ----------------
__device__ float d_G[T * H];        // shared gate raw -> silu writes tf32 bits
__device__ float d_U[T * H];        // shared up raw
__device__ float d_eg[2 * T * IT];  // expert gate raw (stride IT)
__device__ float d_eu[2 * T * IT];  // expert up raw
__device__ float d_act[2 * T * IT]; // silu(eg)*eu
__device__ float d_yp[2 * T * H];   // per-pair expert outputs
__device__ int   d_pairs[2][NE][T];
__device__ int   d_cnt[2][NE];
__device__ float d_wts[T][2];
__device__ int   d_sel[T][2];
__device__ int   d_modal[T];
// tf32-converted operands for the dense (shared-MLP) path
__device__ uint32_t d_xt[T * H];    // x converted
__device__ uint32_t d_sgt[H * H];   // sg transposed+converted [n][k]
__device__ uint32_t d_sut[H * H];   // su transposed+converted
__device__ uint32_t d_sdt[H * H];   // sd transposed+converted

// ---------------- helpers ----------------
__device__ __forceinline__ uint32_t f2tf(float f) {
    uint32_t r;
    asm("cvt.rna.tf32.f32 %0, %1;" : "=r"(r) : "f"(f));
    return r;
}
__device__ __forceinline__ int swz(int r) { return (r + (r >> 2)) & 3; }

__device__ __forceinline__ void mma_tf32(float* c, const uint32_t* a, uint32_t b0, uint32_t b1) {
    asm volatile(
        "mma.sync.aligned.m16n8k8.row.col.f32.tf32.tf32.f32 "
        "{%0,%1,%2,%3}, {%4,%5,%6,%7}, {%8,%9}, {%0,%1,%2,%3};"
        : "+f"(c[0]), "+f"(c[1]), "+f"(c[2]), "+f"(c[3])
        : "r"(a[0]), "r"(a[1]), "r"(a[2]), "r"(a[3]), "r"(b0), "r"(b1));
}

#define CP16(dst32, srcp) \
    asm volatile("cp.async.cg.shared.global [%0], [%1], 16;" :: "r"(dst32), "l"(srcp))
#define CP_COMMIT() asm volatile("cp.async.commit_group;" ::: "memory")
#define CP_WAIT1()  asm volatile("cp.async.wait_group 1;" ::: "memory")

// ---------------- router ----------------
__global__ __launch_bounds__(256) void k_router(
    const float* __restrict__ x, const int* __restrict__ tt,
    const float* __restrict__ Wt, const float* __restrict__ bt,
    const float* __restrict__ Wv, const float* __restrict__ bv,
    float* __restrict__ logits_out)
{
    int lane = threadIdx.x & 31;
    int t = blockIdx.x * 8 + (threadIdx.x >> 5);
    if (t >= T) return;

    int mod = (tt[t] != 0) ? 1 : 0;
    const float* W = mod ? Wv : Wt;
    const float* bias = mod ? bv : bt;

    float4 xr[8];
#pragma unroll
    for (int j = 0; j < 8; ++j)
        xr[j] = *(const float4*)&x[(size_t)t * H + (lane + 32 * j) * 4];

    float logit[NE];
#pragma unroll
    for (int e = 0; e < NE; ++e) {
        const float* w = W + (size_t)e * H;
        float s = 0.f;
#pragma unroll
        for (int j = 0; j < 8; ++j) {
            float4 wv4 = *(const float4*)&w[(lane + 32 * j) * 4];
            s = fmaf(xr[j].x, wv4.x, s);
            s = fmaf(xr[j].y, wv4.y, s);
            s = fmaf(xr[j].z, wv4.z, s);
            s = fmaf(xr[j].w, wv4.w, s);
        }
#pragma unroll
        for (int o = 16; o; o >>= 1) s += __shfl_xor_sync(0xffffffffu, s, o);
        logit[e] = s;
    }

    float mx = logit[0];
#pragma unroll
    for (int e = 1; e < NE; ++e) mx = fmaxf(mx, logit[e]);
    float p[NE], sum = 0.f;
#pragma unroll
    for (int e = 0; e < NE; ++e) { p[e] = expf(logit[e] - mx); sum += p[e]; }
    float inv = 1.f / sum;
#pragma unroll
    for (int e = 0; e < NE; ++e) p[e] *= inv;

    int i0 = 0; float b0 = -1e30f;
#pragma unroll
    for (int e = 0; e < NE; ++e) { float sc = p[e] + bias[e]; if (sc > b0) { b0 = sc; i0 = e; } }
    int i1 = 0; float b1 = -1e30f;
#pragma unroll
    for (int e = 0; e < NE; ++e) {
        if (e == i0) continue;
        float sc = p[e] + bias[e];
        if (sc > b1) { b1 = sc; i1 = e; }
    }
    float w0 = p[i0], w1 = p[i1];
    float s2 = fmaxf(w0 + w1, 1e-12f);
    w0 /= s2; w1 /= s2;

    if (lane < NE) logits_out[(size_t)t * NE + lane] = logit[lane];
    if (lane == 0) {
        d_sel[t][0] = i0; d_sel[t][1] = i1;
        d_wts[t][0] = w0; d_wts[t][1] = w1;
        d_modal[t] = mod;
    }
}

// ---------------- deterministic list build ----------------
__global__ __launch_bounds__(1024) void k_build() {
    int w = threadIdx.x >> 5, lane = threadIdx.x & 31;
    int mod = w >> 4, e = w & 15;
    int cnt = 0;
    for (int base = 0; base < T; base += 32) {
        int t = base + lane;
        int match = 0, slot = 0;
        if (d_modal[t] == mod) {
            if (d_sel[t][0] == e) { match = 1; slot = 0; }
            else if (d_sel[t][1] == e) { match = 1; slot = 1; }
        }
        unsigned m = __ballot_sync(0xffffffffu, match);
        if (match) {
            int pos = cnt + __popc(m & ((1u << lane) - 1u));
            d_pairs[mod][e][pos] = (t << 1) | slot;
        }
        cnt += __popc(m);
    }
    if (lane == 0) d_cnt[mod][e] = cnt;
}

// ---------------- prep: convert x; transpose+convert shared weights ----------------
// z=0: x -> d_xt (convert only). z=1,2,3: sg/su/sd -> [n][k] tf32.
__global__ __launch_bounds__(256) void k_prep(
    const float* __restrict__ x, const float* __restrict__ sg,
    const float* __restrict__ su, const float* __restrict__ sd)
{
    int z = blockIdx.z;
    int tx = threadIdx.x, ty = threadIdx.y;   // 32 x 8
    int bx = blockIdx.x, by = blockIdx.y;
    if (z == 0) {
#pragma unroll
        for (int i = 0; i < 4; ++i) {
            int r = by * 32 + ty + 8 * i;
            int c = bx * 32 + tx;
            d_xt[(size_t)r * H + c] = f2tf(x[(size_t)r * H + c]);
        }
        return;
    }
    const float* src = (z == 1) ? sg : (z == 2) ? su : sd;
    uint32_t* dst = (z == 1) ? d_sgt : (z == 2) ? d_sut : d_sdt;
    __shared__ uint32_t s[32][33];
#pragma unroll
    for (int i = 0; i < 4; ++i) {
        int k = by * 32 + ty + 8 * i;   // source row
        int n = bx * 32 + tx;           // source col
        s[ty + 8 * i][tx] = f2tf(src[(size_t)k * H + n]);
    }
    __syncthreads();
#pragma unroll
    for (int i = 0; i < 4; ++i) {
        int n = bx * 32 + ty + 8 * i;   // dest row (n)
        int k = by * 32 + tx;           // dest col (k)
        dst[(size_t)n * H + k] = s[tx][ty + 8 * i];
    }
}

// ============ dense tf32 core: 128x128 tile, 256 thr, cp.async 3-stage ============
// A [M][K] tf32 row-major (k-contig), B [N][K] tf32 (pre-transposed weights).
// K = H = 1024 fixed. No conversions in the loop.
__device__ __forceinline__ void dense_core(
    const uint32_t* __restrict__ A, const uint32_t* __restrict__ B,
    float* __restrict__ C, int mbase, int nbase)
{
    __shared__ uint32_t sA[3][128 * 16];
    __shared__ uint32_t sB[3][128 * 16];

    const int tid = threadIdx.x;
    const int lane = tid & 31;
    const int warp = tid >> 5;
    const int wm = warp & 3, wn = warp >> 2;   // 4 m-tiles x 2 n-tiles of 32x64
    const int g = lane >> 2, tg = lane & 3;

    const uint32_t saBase = (uint32_t)__cvta_generic_to_shared(&sA[0][0]);
    const uint32_t sbBase = (uint32_t)__cvta_generic_to_shared(&sB[0][0]);

    // chunk mapping: c = tid + 256j -> row = c>>2, kc = c&3 (16B chunk)
    const int r0 = tid >> 2, kc0 = tid & 3;
    const int r1 = (tid + 256) >> 2, kc1 = (tid + 256) & 3;

    auto ISSUE = [&](int s, int kt) {
        {
            const uint32_t* srcA = A + (size_t)(mbase + r0) * H + kt * 16 + kc0 * 4;
            CP16(saBase + (s * 2048 + r0 * 16 + kc0 * 4) * 4, srcA);
            const uint32_t* srcB = B + (size_t)(nbase + r0) * H + kt * 16 + kc0 * 4;
            CP16(sbBase + (s * 2048 + r0 * 16 + kc0 * 4) * 4, srcB);
        }
        {
            const uint32_t* srcA = A + (size_t)(mbase + r1) * H + kt * 16 + kc1 * 4;
            CP16(saBase + (s * 2048 + r1 * 16 + kc1 * 4) * 4, srcA);
            const uint32_t* srcB = B + (size_t)(nbase + r1) * H + kt * 16 + kc1 * 4;
            CP16(sbBase + (s * 2048 + r1 * 16 + kc1 * 4) * 4, srcB);
        }
    };

    float acc[2][8][4];
#pragma unroll
    for (int a = 0; a < 2; ++a)
#pragma unroll
        for (int b = 0; b < 8; ++b)
#pragma unroll
            for (int c = 0; c < 4; ++c) acc[a][b][c] = 0.f;

    auto COMPUTE = [&](int s) {
        uint32_t Af[2][2][4];
#pragma unroll
        for (int fm = 0; fm < 2; ++fm)
#pragma unroll
            for (int rr = 0; rr < 2; ++rr) {
                int m = wm * 32 + fm * 16 + g + rr * 8;
                uint4 v = *(const uint4*)&sA[s][m * 16 + 4 * tg];
                Af[fm][rr][0] = v.x; Af[fm][rr][1] = v.y;
                Af[fm][rr][2] = v.z; Af[fm][rr][3] = v.w;
            }
#pragma unroll
        for (int half = 0; half < 2; ++half) {
            uint32_t Bf[4][4];
#pragma unroll
            for (int f4 = 0; f4 < 4; ++f4) {
                int fn = half * 4 + f4;
                int n = wn * 64 + fn * 8 + g;
                uint4 v = *(const uint4*)&sB[s][n * 16 + 4 * tg];
                Bf[f4][0] = v.x; Bf[f4][1] = v.y; Bf[f4][2] = v.z; Bf[f4][3] = v.w;
            }
#pragma unroll
            for (int kk = 0; kk < 2; ++kk) {
                uint32_t a[2][4];
#pragma unroll
                for (int fm = 0; fm < 2; ++fm) {
                    a[fm][0] = Af[fm][0][2 * kk];
                    a[fm][1] = Af[fm][1][2 * kk];
                    a[fm][2] = Af[fm][0][2 * kk + 1];
                    a[fm][3] = Af[fm][1][2 * kk + 1];
                }
#pragma unroll
                for (int f4 = 0; f4 < 4; ++f4) {
                    int fn = half * 4 + f4;
                    uint32_t b0 = Bf[f4][2 * kk], b1 = Bf[f4][2 * kk + 1];
                    mma_tf32(acc[0][fn], a[0], b0, b1);
                    mma_tf32(acc[1][fn], a[1], b0, b1);
                }
            }
        }
    };

    const int nk = H / 16;   // 64
    ISSUE(0, 0); CP_COMMIT();
    ISSUE(1, 1); CP_COMMIT();
    int s = 0;
    for (int kt = 0; kt < nk; ++kt) {
        CP_WAIT1();
        __syncthreads();
        COMPUTE(s);
        if (kt + 2 < nk) {
            int s2 = s + 2; if (s2 >= 3) s2 -= 3;
            ISSUE(s2, kt + 2);
        }
        CP_COMMIT();
        if (++s == 3) s = 0;
    }

    // epilogue
#pragma unroll
    for (int fm = 0; fm < 2; ++fm) {
#pragma unroll
        for (int h = 0; h < 2; ++h) {
            int ml = wm * 32 + fm * 16 + g + h * 8;
            int crow = mbase + ml;
#pragma unroll
            for (int fn = 0; fn < 8; ++fn) {
                int nc = nbase + wn * 64 + fn * 8 + 2 * tg;
                *(float2*)&C[(size_t)crow * H + nc] =
                    make_float2(acc[fm][fn][2 * h], acc[fm][fn][2 * h + 1]);
            }
        }
    }
}

// z=0: G = x@sg^T-form; z=1: U = x@su
__global__ __launch_bounds__(256) void k_shared1() {
    const uint32_t* Bm = blockIdx.z ? d_sut : d_sgt;
    float* Cm = blockIdx.z ? d_U : d_G;
    dense_core(d_xt, Bm, Cm, blockIdx.x * 128, blockIdx.y * 128);
}

__global__ __launch_bounds__(256) void k_shared2(float* __restrict__ out) {
    dense_core((const uint32_t*)d_G, d_sdt, out, blockIdx.x * 128, blockIdx.y * 128);
}

// ============ expert tf32 core (R9, proven): 64x128, BK=16, 4 warps ============
// gmode: 1 A row = pair>>1, C row = pair; 2 A row = C row = pair
__device__ __forceinline__ void gemm_expert(
    int gmode,
    const float* __restrict__ A, int lda,
    const float* __restrict__ B, int ldb,
    float* __restrict__ C, int ldc,
    int K, int mbase, int nbase,
    const int* __restrict__ plist, int cnt)
{
    __shared__ uint32_t As[2][64][16];
    __shared__ uint32_t Bs[2][128][16];
    __shared__ int rowid[64];

    const int tid = threadIdx.x;
    const int lane = tid & 31;
    const int warp = tid >> 5;
    const int wm = warp & 1, wn = warp >> 1;
    const int g = lane >> 2, tg = lane & 3;

    if (tid < 64) {
        int m = mbase + tid;
        rowid[tid] = (m < cnt) ? plist[m] : -1;
    }
    __syncthreads();

    const float* aptr[2];
    int am[2], akq[2];
#pragma unroll
    for (int j = 0; j < 2; ++j) {
        int f = tid + 128 * j;
        int m = f >> 2;
        int kq = f & 3;
        am[j] = m; akq[j] = kq;
        int pv = rowid[m];
        if (pv < 0) pv = 0;
        int r = (gmode == 1) ? (pv >> 1) : pv;
        aptr[j] = A + (size_t)r * lda + kq * 4;
    }
    const int kqB = warp;
    const int nl = lane;
    const float* bptr = B + (size_t)(4 * kqB) * ldb + nbase + nl;
    const size_t ldb1 = ldb, ldb2 = 2 * (size_t)ldb, ldb3 = 3 * (size_t)ldb;

    float acc[2][8][4];
#pragma unroll
    for (int a = 0; a < 2; ++a)
#pragma unroll
        for (int b = 0; b < 8; ++b)
#pragma unroll
            for (int c = 0; c < 4; ++c) acc[a][b][c] = 0.f;

    float4 ar[2];
    float bv[4][4];

    auto LDG = [&]() {
#pragma unroll
        for (int j = 0; j < 2; ++j) ar[j] = *(const float4*)(aptr[j]);
#pragma unroll
        for (int grp = 0; grp < 4; ++grp) {
            bv[grp][0] = bptr[grp * 32];
            bv[grp][1] = bptr[ldb1 + grp * 32];
            bv[grp][2] = bptr[ldb2 + grp * 32];
            bv[grp][3] = bptr[ldb3 + grp * 32];
        }
        aptr[0] += 16; aptr[1] += 16;
        bptr += 16 * ldb1;
    };
    auto STS = [&](int buf) {
#pragma unroll
        for (int j = 0; j < 2; ++j) {
            int m = am[j];
            uint4 w;
            w.x = f2tf(ar[j].x); w.y = f2tf(ar[j].y);
            w.z = f2tf(ar[j].z); w.w = f2tf(ar[j].w);
            *(uint4*)&As[buf][m][(akq[j] ^ swz(m)) << 2] = w;
        }
#pragma unroll
        for (int grp = 0; grp < 4; ++grp) {
            int n = nl + 32 * grp;
            uint4 w;
            w.x = f2tf(bv[grp][0]); w.y = f2tf(bv[grp][1]);
            w.z = f2tf(bv[grp][2]); w.w = f2tf(bv[grp][3]);
            *(uint4*)&Bs[buf][n][(kqB ^ swz(n)) << 2] = w;
        }
    };
    auto COMPUTE = [&](int buf) {
        uint32_t Af[2][2][4];
#pragma unroll
        for (int fm = 0; fm < 2; ++fm)
#pragma unroll
            for (int rr = 0; rr < 2; ++rr) {
                int m = wm * 32 + fm * 16 + g + rr * 8;
                uint4 v = *(const uint4*)&As[buf][m][(tg ^ swz(m)) << 2];
                Af[fm][rr][0] = v.x; Af[fm][rr][1] = v.y;
                Af[fm][rr][2] = v.z; Af[fm][rr][3] = v.w;
            }
#pragma unroll
        for (int half = 0; half < 2; ++half) {
            uint32_t Bf[4][4];
#pragma unroll
            for (int f4 = 0; f4 < 4; ++f4) {
                int fn = half * 4 + f4;
                int n = wn * 64 + fn * 8 + g;
                uint4 v = *(const uint4*)&Bs[buf][n][(tg ^ swz(n)) << 2];
                Bf[f4][0] = v.x; Bf[f4][1] = v.y; Bf[f4][2] = v.z; Bf[f4][3] = v.w;
            }
#pragma unroll
            for (int kk = 0; kk < 2; ++kk) {
                uint32_t a[2][4];
#pragma unroll
                for (int fm = 0; fm < 2; ++fm) {
                    a[fm][0] = Af[fm][0][2 * kk];
                    a[fm][1] = Af[fm][1][2 * kk];
                    a[fm][2] = Af[fm][0][2 * kk + 1];
                    a[fm][3] = Af[fm][1][2 * kk + 1];
                }
#pragma unroll
                for (int f4 = 0; f4 < 4; ++f4) {
                    int fn = half * 4 + f4;
                    uint32_t b0 = Bf[f4][2 * kk], b1 = Bf[f4][2 * kk + 1];
                    mma_tf32(acc[0][fn], a[0], b0, b1);
                    mma_tf32(acc[1][fn], a[1], b0, b1);
                }
            }
        }
    };

    int nk = K >> 4;
    LDG();
    STS(0);
    __syncthreads();
    for (int kt = 0; kt < nk; ++kt) {
        int cur = kt & 1;
        if (kt + 1 < nk) LDG();
        COMPUTE(cur);
        if (kt + 1 < nk) STS(cur ^ 1);
        __syncthreads();
    }

#pragma unroll
    for (int fm = 0; fm < 2; ++fm) {
#pragma unroll
        for (int h = 0; h < 2; ++h) {
            int ml = wm * 32 + fm * 16 + g + h * 8;
            int pv = rowid[ml];
            if (pv < 0) continue;
#pragma unroll
            for (int fn = 0; fn < 8; ++fn) {
                int nc = nbase + wn * 64 + fn * 8 + 2 * tg;
                *(float2*)&C[(size_t)pv * ldc + nc] =
                    make_float2(acc[fm][fn][2 * h], acc[fm][fn][2 * h + 1]);
            }
        }
    }
}

// ---------------- expert pass 1: gate (z<32) / up (z>=32) ----------------
__global__ __launch_bounds__(128) void k_egemm1(
    const float* __restrict__ x, const float* __restrict__ tgu, const float* __restrict__ vgu)
{
    int z = blockIdx.z;
    int mbase = blockIdx.x * 64;
    int nbase = blockIdx.y * 128;
    int isup = (z >= 32);
    int idx = z & 31;
    int mod = idx >> 4, e = idx & 15;
    int cnt = d_cnt[mod][e];
    if (mbase >= cnt) return;
    int I = mod ? IV : IT;
    if (nbase >= I) return;
    const float* gup = (mod ? vgu : tgu) + (size_t)e * H * 2 * I + (isup ? I : 0);
    float* Cm = isup ? d_eu : d_eg;
    gemm_expert(1, x, H, gup, 2 * I, Cm, IT, H,
                mbase, nbase, &d_pairs[mod][e][0], cnt);
}

// ---------------- silu: shared region writes tf32 bits (feeds dense shared2) ----------------
__global__ __launch_bounds__(256) void k_silu() {
    int gid = blockIdx.x * blockDim.x + threadIdx.x;  // float4 units, 524288 total
    const int NG = (T * H) / 4;
    if (gid < NG) {
        float4 gv = ((const float4*)d_G)[gid];
        float4 uv = ((const float4*)d_U)[gid];
        uint4 o;
        o.x = f2tf((gv.x / (1.f + __expf(-gv.x))) * uv.x);
        o.y = f2tf((gv.y / (1.f + __expf(-gv.y))) * uv.y);
        o.z = f2tf((gv.z / (1.f + __expf(-gv.z))) * uv.z);
        o.w = f2tf((gv.w / (1.f + __expf(-gv.w))) * uv.w);
        ((uint4*)d_G)[gid] = o;
    } else {
        int p = gid - NG;
        float4 gv = ((const float4*)d_eg)[p];
        float4 uv = ((const float4*)d_eu)[p];
        float4 o;
        o.x = (gv.x / (1.f + __expf(-gv.x))) * uv.x;
        o.y = (gv.y / (1.f + __expf(-gv.y))) * uv.y;
        o.z = (gv.z / (1.f + __expf(-gv.z))) * uv.z;
        o.w = (gv.w / (1.f + __expf(-gv.w))) * uv.w;
        ((float4*)d_act)[p] = o;
    }
}

// ---------------- expert pass 2: down ----------------
__global__ __launch_bounds__(128) void k_egemm2(
    const float* __restrict__ tdn, const float* __restrict__ vdn)
{
    int z = blockIdx.z;
    int mbase = blockIdx.x * 64;
    int nbase = blockIdx.y * 128;
    int mod = z >> 4, e = z & 15;
    int cnt = d_cnt[mod][e];
    if (mbase >= cnt) return;
    int I = mod ? IV : IT;
    const float* dn = (mod ? vdn : tdn) + (size_t)e * I * H;
    gemm_expert(2, d_act, IT, dn, H, d_yp, H, I,
                mbase, nbase, &d_pairs[mod][e][0], cnt);
}

// ---------------- final combine ----------------
__global__ __launch_bounds__(256) void k_combine(float* __restrict__ out) {
    int gid = blockIdx.x * blockDim.x + threadIdx.x;   // float4 units
    int t = gid >> 8;
    int c4 = gid & 255;
    float w0 = d_wts[t][0], w1 = d_wts[t][1];
    float4 o = ((float4*)out)[gid];
    float4 a = ((const float4*)&d_yp[(size_t)(2 * t) * H])[c4];
    float4 b = ((const float4*)&d_yp[(size_t)(2 * t + 1) * H])[c4];
    o.x += w0 * a.x + w1 * b.x;
    o.y += w0 * a.y + w1 * b.y;
    o.z += w0 * a.z + w1 * b.z;
    o.w += w0 * a.w + w1 * b.w;
    ((float4*)out)[gid] = o;
}

// ---------------- launch ----------------
extern "C" void kernel_launch(void* const* d_in, const int* in_sizes, int n_in,
                              void* d_out, int out_size)
{
    const float* x   = (const float*)d_in[0];
    const int*   tt  = (const int*)d_in[1];
    const float* trw = (const float*)d_in[2];
    const float* tb  = (const float*)d_in[3];
    const float* tgu = (const float*)d_in[4];
    const float* tdn = (const float*)d_in[5];
    const float* vrw = (const float*)d_in[6];
    const float* vb  = (const float*)d_in[7];
    const float* vgu = (const float*)d_in[8];
    const float* vdn = (const float*)d_in[9];
    const float* sg  = (const float*)d_in[10];
    const float* su  = (const float*)d_in[11];
    const float* sd  = (const float*)d_in[12];

    float* out = (float*)d_out;
    float* logits = out + (size_t)T * H;

    k_prep<<<dim3(32, 32, 4), dim3(32, 8)>>>(x, sg, su, sd);
    k_router<<<128, 256>>>(x, tt, trw, tb, vrw, vb, logits);
    k_build<<<1, 1024>>>();
    k_shared1<<<dim3(8, 8, 2), 256>>>();
    k_egemm1<<<dim3(16, 8, 64), 128>>>(x, tgu, vgu);
    k_silu<<<2048, 256>>>();
    k_shared2<<<dim3(8, 8), 256>>>(out);
    k_egemm2<<<dim3(16, 8, 32), 128>>>(tdn, vdn);
    k_combine<<<1024, 256>>>(out);
}

// round 14
// speedup vs baseline: 1.2183x; 1.0108x over previous
#include <cuda_runtime.h>
#include <cstdint>

#define H 1024
#define T 1024
#define NE 16
#define IT 512
#define IV 256

// ---------------- scratch ----------------
__device__ float d_G[T * H];
__device__ float d_U[T * H];
__device__ float d_eg[2 * T * IT];
__device__ float d_eu[2 * T * IT];
__device__ float d_eg2[2 * T * IT];   // K-split partial (half 1)
__device__ float d_eu2[2 * T * IT];
__device__ float d_act[2 * T * IT];
__device__ float d_yp[2 * T * H];
__device__ float d_yp2[2 * T * H];    // K-split partial (half 1)
__device__ int   d_pairs[2][NE][T];
__device__ int   d_cnt[2][NE];
__device__ float d_wts[T][2];
__device__ int   d_sel[T][2];
__device__ int   d_modal[T];
__device__ uint32_t d_xt[T * H];
__device__ uint32_t d_sgt[H * H];
__device__ uint32_t d_sut[H * H];
__device__ uint32_t d_sdt[H * H];

// ---------------- helpers ----------------
__device__ __forceinline__ uint32_t f2tf(float f) {
    uint32_t r;
    asm("cvt.rna.tf32.f32 %0, %1;" : "=r"(r) : "f"(f));
    return r;
}
__device__ __forceinline__ int swz(int r) { return (r + (r >> 2)) & 3; }

__device__ __forceinline__ void mma_tf32(float* c, const uint32_t* a, uint32_t b0, uint32_t b1) {
    asm volatile(
        "mma.sync.aligned.m16n8k8.row.col.f32.tf32.tf32.f32 "
        "{%0,%1,%2,%3}, {%4,%5,%6,%7}, {%8,%9}, {%0,%1,%2,%3};"
        : "+f"(c[0]), "+f"(c[1]), "+f"(c[2]), "+f"(c[3])
        : "r"(a[0]), "r"(a[1]), "r"(a[2]), "r"(a[3]), "r"(b0), "r"(b1));
}

#define CP16(dst32, srcp) \
    asm volatile("cp.async.cg.shared.global [%0], [%1], 16;" :: "r"(dst32), "l"(srcp))
#define CP_COMMIT() asm volatile("cp.async.commit_group;" ::: "memory")
#define CP_WAIT3()  asm volatile("cp.async.wait_group 3;" ::: "memory")

// ---------------- router ----------------
__global__ __launch_bounds__(256) void k_router(
    const float* __restrict__ x, const int* __restrict__ tt,
    const float* __restrict__ Wt, const float* __restrict__ bt,
    const float* __restrict__ Wv, const float* __restrict__ bv,
    float* __restrict__ logits_out)
{
    int lane = threadIdx.x & 31;
    int t = blockIdx.x * 8 + (threadIdx.x >> 5);
    if (t >= T) return;

    int mod = (tt[t] != 0) ? 1 : 0;
    const float* W = mod ? Wv : Wt;
    const float* bias = mod ? bv : bt;

    float4 xr[8];
#pragma unroll
    for (int j = 0; j < 8; ++j)
        xr[j] = *(const float4*)&x[(size_t)t * H + (lane + 32 * j) * 4];

    float logit[NE];
#pragma unroll
    for (int e = 0; e < NE; ++e) {
        const float* w = W + (size_t)e * H;
        float s = 0.f;
#pragma unroll
        for (int j = 0; j < 8; ++j) {
            float4 wv4 = *(const float4*)&w[(lane + 32 * j) * 4];
            s = fmaf(xr[j].x, wv4.x, s);
            s = fmaf(xr[j].y, wv4.y, s);
            s = fmaf(xr[j].z, wv4.z, s);
            s = fmaf(xr[j].w, wv4.w, s);
        }
#pragma unroll
        for (int o = 16; o; o >>= 1) s += __shfl_xor_sync(0xffffffffu, s, o);
        logit[e] = s;
    }

    float mx = logit[0];
#pragma unroll
    for (int e = 1; e < NE; ++e) mx = fmaxf(mx, logit[e]);
    float p[NE], sum = 0.f;
#pragma unroll
    for (int e = 0; e < NE; ++e) { p[e] = expf(logit[e] - mx); sum += p[e]; }
    float inv = 1.f / sum;
#pragma unroll
    for (int e = 0; e < NE; ++e) p[e] *= inv;

    int i0 = 0; float b0 = -1e30f;
#pragma unroll
    for (int e = 0; e < NE; ++e) { float sc = p[e] + bias[e]; if (sc > b0) { b0 = sc; i0 = e; } }
    int i1 = 0; float b1 = -1e30f;
#pragma unroll
    for (int e = 0; e < NE; ++e) {
        if (e == i0) continue;
        float sc = p[e] + bias[e];
        if (sc > b1) { b1 = sc; i1 = e; }
    }
    float w0 = p[i0], w1 = p[i1];
    float s2 = fmaxf(w0 + w1, 1e-12f);
    w0 /= s2; w1 /= s2;

    if (lane < NE) logits_out[(size_t)t * NE + lane] = logit[lane];
    if (lane == 0) {
        d_sel[t][0] = i0; d_sel[t][1] = i1;
        d_wts[t][0] = w0; d_wts[t][1] = w1;
        d_modal[t] = mod;
    }
}

// ---------------- deterministic list build ----------------
__global__ __launch_bounds__(1024) void k_build() {
    int w = threadIdx.x >> 5, lane = threadIdx.x & 31;
    int mod = w >> 4, e = w & 15;
    int cnt = 0;
    for (int base = 0; base < T; base += 32) {
        int t = base + lane;
        int match = 0, slot = 0;
        if (d_modal[t] == mod) {
            if (d_sel[t][0] == e) { match = 1; slot = 0; }
            else if (d_sel[t][1] == e) { match = 1; slot = 1; }
        }
        unsigned m = __ballot_sync(0xffffffffu, match);
        if (match) {
            int pos = cnt + __popc(m & ((1u << lane) - 1u));
            d_pairs[mod][e][pos] = (t << 1) | slot;
        }
        cnt += __popc(m);
    }
    if (lane == 0) d_cnt[mod][e] = cnt;
}

// ---------------- prep ----------------
__global__ __launch_bounds__(256) void k_prep(
    const float* __restrict__ x, const float* __restrict__ sg,
    const float* __restrict__ su, const float* __restrict__ sd)
{
    int z = blockIdx.z;
    int tx = threadIdx.x, ty = threadIdx.y;   // 32 x 8
    int bx = blockIdx.x, by = blockIdx.y;
    if (z == 0) {
#pragma unroll
        for (int i = 0; i < 4; ++i) {
            int r = by * 32 + ty + 8 * i;
            int c = bx * 32 + tx;
            d_xt[(size_t)r * H + c] = f2tf(x[(size_t)r * H + c]);
        }
        return;
    }
    const float* src = (z == 1) ? sg : (z == 2) ? su : sd;
    uint32_t* dst = (z == 1) ? d_sgt : (z == 2) ? d_sut : d_sdt;
    __shared__ uint32_t s[32][33];
#pragma unroll
    for (int i = 0; i < 4; ++i) {
        int k = by * 32 + ty + 8 * i;
        int n = bx * 32 + tx;
        s[ty + 8 * i][tx] = f2tf(src[(size_t)k * H + n]);
    }
    __syncthreads();
#pragma unroll
    for (int i = 0; i < 4; ++i) {
        int n = bx * 32 + ty + 8 * i;
        int k = by * 32 + tx;
        dst[(size_t)n * H + k] = s[tx][ty + 8 * i];
    }
}

// ============ dense tf32 core: 128x128 tile, 256 thr, cp.async 5-stage ============
#define DSTAGES 5
__device__ __forceinline__ void dense_core(
    const uint32_t* __restrict__ A, const uint32_t* __restrict__ B,
    float* __restrict__ C, int mbase, int nbase)
{
    extern __shared__ uint32_t dsm[];
    uint32_t* sA = dsm;                       // [DSTAGES][2048]
    uint32_t* sB = dsm + DSTAGES * 2048;      // [DSTAGES][2048]

    const int tid = threadIdx.x;
    const int lane = tid & 31;
    const int warp = tid >> 5;
    const int wm = warp & 3, wn = warp >> 2;
    const int g = lane >> 2, tg = lane & 3;

    const uint32_t saBase = (uint32_t)__cvta_generic_to_shared(sA);
    const uint32_t sbBase = (uint32_t)__cvta_generic_to_shared(sB);

    const int r0 = tid >> 2, kc0 = tid & 3;
    const int r1 = (tid + 256) >> 2, kc1 = (tid + 256) & 3;

    auto ISSUE = [&](int s, int kt) {
        {
            const uint32_t* srcA = A + (size_t)(mbase + r0) * H + kt * 16 + kc0 * 4;
            CP16(saBase + (s * 2048 + r0 * 16 + kc0 * 4) * 4, srcA);
            const uint32_t* srcB = B + (size_t)(nbase + r0) * H + kt * 16 + kc0 * 4;
            CP16(sbBase + (s * 2048 + r0 * 16 + kc0 * 4) * 4, srcB);
        }
        {
            const uint32_t* srcA = A + (size_t)(mbase + r1) * H + kt * 16 + kc1 * 4;
            CP16(saBase + (s * 2048 + r1 * 16 + kc1 * 4) * 4, srcA);
            const uint32_t* srcB = B + (size_t)(nbase + r1) * H + kt * 16 + kc1 * 4;
            CP16(sbBase + (s * 2048 + r1 * 16 + kc1 * 4) * 4, srcB);
        }
    };

    float acc[2][8][4];
#pragma unroll
    for (int a = 0; a < 2; ++a)
#pragma unroll
        for (int b = 0; b < 8; ++b)
#pragma unroll
            for (int c = 0; c < 4; ++c) acc[a][b][c] = 0.f;

    auto COMPUTE = [&](int s) {
        uint32_t Af[2][2][4];
#pragma unroll
        for (int fm = 0; fm < 2; ++fm)
#pragma unroll
            for (int rr = 0; rr < 2; ++rr) {
                int m = wm * 32 + fm * 16 + g + rr * 8;
                uint4 v = *(const uint4*)&sA[s * 2048 + m * 16 + 4 * tg];
                Af[fm][rr][0] = v.x; Af[fm][rr][1] = v.y;
                Af[fm][rr][2] = v.z; Af[fm][rr][3] = v.w;
            }
#pragma unroll
        for (int half = 0; half < 2; ++half) {
            uint32_t Bf[4][4];
#pragma unroll
            for (int f4 = 0; f4 < 4; ++f4) {
                int fn = half * 4 + f4;
                int n = wn * 64 + fn * 8 + g;
                uint4 v = *(const uint4*)&sB[s * 2048 + n * 16 + 4 * tg];
                Bf[f4][0] = v.x; Bf[f4][1] = v.y; Bf[f4][2] = v.z; Bf[f4][3] = v.w;
            }
#pragma unroll
            for (int kk = 0; kk < 2; ++kk) {
                uint32_t a[2][4];
#pragma unroll
                for (int fm = 0; fm < 2; ++fm) {
                    a[fm][0] = Af[fm][0][2 * kk];
                    a[fm][1] = Af[fm][1][2 * kk];
                    a[fm][2] = Af[fm][0][2 * kk + 1];
                    a[fm][3] = Af[fm][1][2 * kk + 1];
                }
#pragma unroll
                for (int f4 = 0; f4 < 4; ++f4) {
                    int fn = half * 4 + f4;
                    uint32_t b0 = Bf[f4][2 * kk], b1 = Bf[f4][2 * kk + 1];
                    mma_tf32(acc[0][fn], a[0], b0, b1);
                    mma_tf32(acc[1][fn], a[1], b0, b1);
                }
            }
        }
    };

    const int nk = H / 16;   // 64
#pragma unroll
    for (int p = 0; p < 4; ++p) { ISSUE(p, p); CP_COMMIT(); }
    int s = 0;
    for (int kt = 0; kt < nk; ++kt) {
        CP_WAIT3();
        __syncthreads();
        COMPUTE(s);
        if (kt + 4 < nk) {
            int s4 = s + 4; if (s4 >= DSTAGES) s4 -= DSTAGES;
            ISSUE(s4, kt + 4);
        }
        CP_COMMIT();
        if (++s == DSTAGES) s = 0;
    }

#pragma unroll
    for (int fm = 0; fm < 2; ++fm) {
#pragma unroll
        for (int h = 0; h < 2; ++h) {
            int ml = wm * 32 + fm * 16 + g + h * 8;
            int crow = mbase + ml;
#pragma unroll
            for (int fn = 0; fn < 8; ++fn) {
                int nc = nbase + wn * 64 + fn * 8 + 2 * tg;
                *(float2*)&C[(size_t)crow * H + nc] =
                    make_float2(acc[fm][fn][2 * h], acc[fm][fn][2 * h + 1]);
            }
        }
    }
}

__global__ __launch_bounds__(256) void k_shared1() {
    const uint32_t* Bm = blockIdx.z ? d_sut : d_sgt;
    float* Cm = blockIdx.z ? d_U : d_G;
    dense_core(d_xt, Bm, Cm, blockIdx.x * 128, blockIdx.y * 128);
}

__global__ __launch_bounds__(256) void k_shared2(float* __restrict__ out) {
    dense_core((const uint32_t*)d_G, d_sdt, out, blockIdx.x * 128, blockIdx.y * 128);
}

// ============ expert tf32 core: 64x128, BK=16, 4 warps, K-split via kbase ============
__device__ __forceinline__ void gemm_expert(
    int gmode,
    const float* __restrict__ A, int lda,
    const float* __restrict__ B, int ldb,
    float* __restrict__ C, int ldc,
    int K, int kbase, int mbase, int nbase,
    const int* __restrict__ plist, int cnt)
{
    __shared__ uint32_t As[2][64][16];
    __shared__ uint32_t Bs[2][128][16];
    __shared__ int rowid[64];

    const int tid = threadIdx.x;
    const int lane = tid & 31;
    const int warp = tid >> 5;
    const int wm = warp & 1, wn = warp >> 1;
    const int g = lane >> 2, tg = lane & 3;

    if (tid < 64) {
        int m = mbase + tid;
        rowid[tid] = (m < cnt) ? plist[m] : -1;
    }
    __syncthreads();

    const float* aptr[2];
    int am[2], akq[2];
#pragma unroll
    for (int j = 0; j < 2; ++j) {
        int f = tid + 128 * j;
        int m = f >> 2;
        int kq = f & 3;
        am[j] = m; akq[j] = kq;
        int pv = rowid[m];
        if (pv < 0) pv = 0;
        int r = (gmode == 1) ? (pv >> 1) : pv;
        aptr[j] = A + (size_t)r * lda + kbase + kq * 4;
    }
    const int kqB = warp;
    const int nl = lane;
    const float* bptr = B + (size_t)(kbase + 4 * kqB) * ldb + nbase + nl;
    const size_t ldb1 = ldb, ldb2 = 2 * (size_t)ldb, ldb3 = 3 * (size_t)ldb;

    float acc[2][8][4];
#pragma unroll
    for (int a = 0; a < 2; ++a)
#pragma unroll
        for (int b = 0; b < 8; ++b)
#pragma unroll
            for (int c = 0; c < 4; ++c) acc[a][b][c] = 0.f;

    float4 ar[2];
    float bv[4][4];

    auto LDG = [&]() {
#pragma unroll
        for (int j = 0; j < 2; ++j) ar[j] = *(const float4*)(aptr[j]);
#pragma unroll
        for (int grp = 0; grp < 4; ++grp) {
            bv[grp][0] = bptr[grp * 32];
            bv[grp][1] = bptr[ldb1 + grp * 32];
            bv[grp][2] = bptr[ldb2 + grp * 32];
            bv[grp][3] = bptr[ldb3 + grp * 32];
        }
        aptr[0] += 16; aptr[1] += 16;
        bptr += 16 * ldb1;
    };
    auto STS = [&](int buf) {
#pragma unroll
        for (int j = 0; j < 2; ++j) {
            int m = am[j];
            uint4 w;
            w.x = f2tf(ar[j].x); w.y = f2tf(ar[j].y);
            w.z = f2tf(ar[j].z); w.w = f2tf(ar[j].w);
            *(uint4*)&As[buf][m][(akq[j] ^ swz(m)) << 2] = w;
        }
#pragma unroll
        for (int grp = 0; grp < 4; ++grp) {
            int n = nl + 32 * grp;
            uint4 w;
            w.x = f2tf(bv[grp][0]); w.y = f2tf(bv[grp][1]);
            w.z = f2tf(bv[grp][2]); w.w = f2tf(bv[grp][3]);
            *(uint4*)&Bs[buf][n][(kqB ^ swz(n)) << 2] = w;
        }
    };
    auto COMPUTE = [&](int buf) {
        uint32_t Af[2][2][4];
#pragma unroll
        for (int fm = 0; fm < 2; ++fm)
#pragma unroll
            for (int rr = 0; rr < 2; ++rr) {
                int m = wm * 32 + fm * 16 + g + rr * 8;
                uint4 v = *(const uint4*)&As[buf][m][(tg ^ swz(m)) << 2];
                Af[fm][rr][0] = v.x; Af[fm][rr][1] = v.y;
                Af[fm][rr][2] = v.z; Af[fm][rr][3] = v.w;
            }
#pragma unroll
        for (int half = 0; half < 2; ++half) {
            uint32_t Bf[4][4];
#pragma unroll
            for (int f4 = 0; f4 < 4; ++f4) {
                int fn = half * 4 + f4;
                int n = wn * 64 + fn * 8 + g;
                uint4 v = *(const uint4*)&Bs[buf][n][(tg ^ swz(n)) << 2];
                Bf[f4][0] = v.x; Bf[f4][1] = v.y; Bf[f4][2] = v.z; Bf[f4][3] = v.w;
            }
#pragma unroll
            for (int kk = 0; kk < 2; ++kk) {
                uint32_t a[2][4];
#pragma unroll
                for (int fm = 0; fm < 2; ++fm) {
                    a[fm][0] = Af[fm][0][2 * kk];
                    a[fm][1] = Af[fm][1][2 * kk];
                    a[fm][2] = Af[fm][0][2 * kk + 1];
                    a[fm][3] = Af[fm][1][2 * kk + 1];
                }
#pragma unroll
                for (int f4 = 0; f4 < 4; ++f4) {
                    int fn = half * 4 + f4;
                    uint32_t b0 = Bf[f4][2 * kk], b1 = Bf[f4][2 * kk + 1];
                    mma_tf32(acc[0][fn], a[0], b0, b1);
                    mma_tf32(acc[1][fn], a[1], b0, b1);
                }
            }
        }
    };

    int nk = K >> 4;
    LDG();
    STS(0);
    __syncthreads();
    for (int kt = 0; kt < nk; ++kt) {
        int cur = kt & 1;
        if (kt + 1 < nk) LDG();
        COMPUTE(cur);
        if (kt + 1 < nk) STS(cur ^ 1);
        __syncthreads();
    }

#pragma unroll
    for (int fm = 0; fm < 2; ++fm) {
#pragma unroll
        for (int h = 0; h < 2; ++h) {
            int ml = wm * 32 + fm * 16 + g + h * 8;
            int pv = rowid[ml];
            if (pv < 0) continue;
#pragma unroll
            for (int fn = 0; fn < 8; ++fn) {
                int nc = nbase + wn * 64 + fn * 8 + 2 * tg;
                *(float2*)&C[(size_t)pv * ldc + nc] =
                    make_float2(acc[fm][fn][2 * h], acc[fm][fn][2 * h + 1]);
            }
        }
    }
}

// ---------------- expert pass 1: z = khalf(1b) | isup(1b) | mod/e(5b) ----------------
__global__ __launch_bounds__(128) void k_egemm1(
    const float* __restrict__ x, const float* __restrict__ tgu, const float* __restrict__ vgu)
{
    int z = blockIdx.z;
    int khalf = z >> 6;
    int zz = z & 63;
    int isup = (zz >= 32);
    int idx = zz & 31;
    int mod = idx >> 4, e = idx & 15;
    int cnt = d_cnt[mod][e];
    int mbase = blockIdx.x * 64;
    if (mbase >= cnt) return;
    int I = mod ? IV : IT;
    int nbase = blockIdx.y * 128;
    if (nbase >= I) return;
    const float* gup = (mod ? vgu : tgu) + (size_t)e * H * 2 * I + (isup ? I : 0);
    float* Cm = isup ? (khalf ? d_eu2 : d_eu) : (khalf ? d_eg2 : d_eg);
    gemm_expert(1, x, H, gup, 2 * I, Cm, IT, 512, khalf * 512,
                mbase, nbase, &d_pairs[mod][e][0], cnt);
}

// ---------------- silu: sums K-split halves; shared region -> tf32 bits ----------------
__global__ __launch_bounds__(256) void k_silu() {
    int gid = blockIdx.x * blockDim.x + threadIdx.x;
    const int NG = (T * H) / 4;
    if (gid < NG) {
        float4 gv = ((const float4*)d_G)[gid];
        float4 uv = ((const float4*)d_U)[gid];
        uint4 o;
        o.x = f2tf((gv.x / (1.f + __expf(-gv.x))) * uv.x);
        o.y = f2tf((gv.y / (1.f + __expf(-gv.y))) * uv.y);
        o.z = f2tf((gv.z / (1.f + __expf(-gv.z))) * uv.z);
        o.w = f2tf((gv.w / (1.f + __expf(-gv.w))) * uv.w);
        ((uint4*)d_G)[gid] = o;
    } else {
        int p = gid - NG;
        float4 g1 = ((const float4*)d_eg)[p];
        float4 g2 = ((const float4*)d_eg2)[p];
        float4 u1 = ((const float4*)d_eu)[p];
        float4 u2 = ((const float4*)d_eu2)[p];
        float gx = g1.x + g2.x, gy = g1.y + g2.y, gz = g1.z + g2.z, gw = g1.w + g2.w;
        float ux = u1.x + u2.x, uy = u1.y + u2.y, uz = u1.z + u2.z, uw = u1.w + u2.w;
        float4 o;
        o.x = (gx / (1.f + __expf(-gx))) * ux;
        o.y = (gy / (1.f + __expf(-gy))) * uy;
        o.z = (gz / (1.f + __expf(-gz))) * uz;
        o.w = (gw / (1.f + __expf(-gw))) * uw;
        ((float4*)d_act)[p] = o;
    }
}

// ---------------- expert pass 2: z = khalf(1b) | mod/e(5b) ----------------
__global__ __launch_bounds__(128) void k_egemm2(
    const float* __restrict__ tdn, const float* __restrict__ vdn)
{
    int z = blockIdx.z;
    int khalf = z >> 5;
    int idx = z & 31;
    int mod = idx >> 4, e = idx & 15;
    int cnt = d_cnt[mod][e];
    int mbase = blockIdx.x * 64;
    if (mbase >= cnt) return;
    int I = mod ? IV : IT;
    int nbase = blockIdx.y * 128;
    const float* dn = (mod ? vdn : tdn) + (size_t)e * I * H;
    int Khalf = I >> 1;
    float* Cm = khalf ? d_yp2 : d_yp;
    gemm_expert(2, d_act, IT, dn, H, Cm, H, Khalf, khalf * Khalf,
                mbase, nbase, &d_pairs[mod][e][0], cnt);
}

// ---------------- final combine: sums K-split halves ----------------
__global__ __launch_bounds__(256) void k_combine(float* __restrict__ out) {
    int gid = blockIdx.x * blockDim.x + threadIdx.x;
    int t = gid >> 8;
    int c4 = gid & 255;
    float w0 = d_wts[t][0], w1 = d_wts[t][1];
    float4 o = ((float4*)out)[gid];
    float4 a1 = ((const float4*)&d_yp[(size_t)(2 * t) * H])[c4];
    float4 a2 = ((const float4*)&d_yp2[(size_t)(2 * t) * H])[c4];
    float4 b1 = ((const float4*)&d_yp[(size_t)(2 * t + 1) * H])[c4];
    float4 b2 = ((const float4*)&d_yp2[(size_t)(2 * t + 1) * H])[c4];
    o.x += w0 * (a1.x + a2.x) + w1 * (b1.x + b2.x);
    o.y += w0 * (a1.y + a2.y) + w1 * (b1.y + b2.y);
    o.z += w0 * (a1.z + a2.z) + w1 * (b1.z + b2.z);
    o.w += w0 * (a1.w + a2.w) + w1 * (b1.w + b2.w);
    ((float4*)out)[gid] = o;
}

// ---------------- launch ----------------
extern "C" void kernel_launch(void* const* d_in, const int* in_sizes, int n_in,
                              void* d_out, int out_size)
{
    const float* x   = (const float*)d_in[0];
    const int*   tt  = (const int*)d_in[1];
    const float* trw = (const float*)d_in[2];
    const float* tb  = (const float*)d_in[3];
    const float* tgu = (const float*)d_in[4];
    const float* tdn = (const float*)d_in[5];
    const float* vrw = (const float*)d_in[6];
    const float* vb  = (const float*)d_in[7];
    const float* vgu = (const float*)d_in[8];
    const float* vdn = (const float*)d_in[9];
    const float* sg  = (const float*)d_in[10];
    const float* su  = (const float*)d_in[11];
    const float* sd  = (const float*)d_in[12];

    float* out = (float*)d_out;
    float* logits = out + (size_t)T * H;

    const int DSM = DSTAGES * 2048 * 2 * 4;   // 81920 bytes
    static int attr_done = 0;
    if (!attr_done) {
        cudaFuncSetAttribute(k_shared1, cudaFuncAttributeMaxDynamicSharedMemorySize, DSM);
        cudaFuncSetAttribute(k_shared2, cudaFuncAttributeMaxDynamicSharedMemorySize, DSM);
        attr_done = 1;
    }

    k_prep<<<dim3(32, 32, 4), dim3(32, 8)>>>(x, sg, su, sd);
    k_router<<<128, 256>>>(x, tt, trw, tb, vrw, vb, logits);
    k_build<<<1, 1024>>>();
    k_shared1<<<dim3(8, 8, 2), 256, DSM>>>();
    k_egemm1<<<dim3(16, 8, 128), 128>>>(x, tgu, vgu);
    k_silu<<<2048, 256>>>();
    k_shared2<<<dim3(8, 8), 256, DSM>>>(out);
    k_egemm2<<<dim3(16, 8, 64), 128>>>(tdn, vdn);
    k_combine<<<1024, 256>>>(out);
}

// round 15
// speedup vs baseline: 1.3007x; 1.0676x over previous
#include <cuda_runtime.h>
#include <cstdint>

#define H 1024
#define T 1024
#define NE 16
#define IT 512
#define IV 256

// ---------------- scratch ----------------
__device__ float d_G[T * H];
__device__ float d_U[T * H];
__device__ float d_eg[2 * T * IT];
__device__ float d_eu[2 * T * IT];
__device__ float d_eg2[2 * T * IT];   // K-split partial (half 1)
__device__ float d_eu2[2 * T * IT];
__device__ float d_act[2 * T * IT];
__device__ float d_yp[2 * T * H];
__device__ float d_yp2[2 * T * H];    // K-split partial (half 1)
__device__ int   d_pairs[2][NE][T];
__device__ int   d_cnt[2][NE];
__device__ float d_wts[T][2];
__device__ int   d_sel[T][2];
__device__ int   d_modal[T];
__device__ uint32_t d_xt[T * H];
__device__ uint32_t d_sgt[H * H];
__device__ uint32_t d_sut[H * H];
__device__ uint32_t d_sdt[H * H];

// ---------------- helpers ----------------
__device__ __forceinline__ uint32_t f2tf(float f) {
    uint32_t r;
    asm("cvt.rna.tf32.f32 %0, %1;" : "=r"(r) : "f"(f));
    return r;
}
__device__ __forceinline__ int swz(int r) { return (r + (r >> 2)) & 3; }

__device__ __forceinline__ void mma_tf32(float* c, const uint32_t* a, uint32_t b0, uint32_t b1) {
    asm volatile(
        "mma.sync.aligned.m16n8k8.row.col.f32.tf32.tf32.f32 "
        "{%0,%1,%2,%3}, {%4,%5,%6,%7}, {%8,%9}, {%0,%1,%2,%3};"
        : "+f"(c[0]), "+f"(c[1]), "+f"(c[2]), "+f"(c[3])
        : "r"(a[0]), "r"(a[1]), "r"(a[2]), "r"(a[3]), "r"(b0), "r"(b1));
}

#define CP16(dst32, srcp) \
    asm volatile("cp.async.cg.shared.global [%0], [%1], 16;" :: "r"(dst32), "l"(srcp))
#define CP_COMMIT() asm volatile("cp.async.commit_group;" ::: "memory")
#define CP_WAIT3()  asm volatile("cp.async.wait_group 3;" ::: "memory")

// ---------------- router ----------------
__global__ __launch_bounds__(256) void k_router(
    const float* __restrict__ x, const int* __restrict__ tt,
    const float* __restrict__ Wt, const float* __restrict__ bt,
    const float* __restrict__ Wv, const float* __restrict__ bv,
    float* __restrict__ logits_out)
{
    int lane = threadIdx.x & 31;
    int t = blockIdx.x * 8 + (threadIdx.x >> 5);
    if (t >= T) return;

    int mod = (tt[t] != 0) ? 1 : 0;
    const float* W = mod ? Wv : Wt;
    const float* bias = mod ? bv : bt;

    float4 xr[8];
#pragma unroll
    for (int j = 0; j < 8; ++j)
        xr[j] = *(const float4*)&x[(size_t)t * H + (lane + 32 * j) * 4];

    float logit[NE];
#pragma unroll
    for (int e = 0; e < NE; ++e) {
        const float* w = W + (size_t)e * H;
        float s = 0.f;
#pragma unroll
        for (int j = 0; j < 8; ++j) {
            float4 wv4 = *(const float4*)&w[(lane + 32 * j) * 4];
            s = fmaf(xr[j].x, wv4.x, s);
            s = fmaf(xr[j].y, wv4.y, s);
            s = fmaf(xr[j].z, wv4.z, s);
            s = fmaf(xr[j].w, wv4.w, s);
        }
#pragma unroll
        for (int o = 16; o; o >>= 1) s += __shfl_xor_sync(0xffffffffu, s, o);
        logit[e] = s;
    }

    float mx = logit[0];
#pragma unroll
    for (int e = 1; e < NE; ++e) mx = fmaxf(mx, logit[e]);
    float p[NE], sum = 0.f;
#pragma unroll
    for (int e = 0; e < NE; ++e) { p[e] = expf(logit[e] - mx); sum += p[e]; }
    float inv = 1.f / sum;
#pragma unroll
    for (int e = 0; e < NE; ++e) p[e] *= inv;

    int i0 = 0; float b0 = -1e30f;
#pragma unroll
    for (int e = 0; e < NE; ++e) { float sc = p[e] + bias[e]; if (sc > b0) { b0 = sc; i0 = e; } }
    int i1 = 0; float b1 = -1e30f;
#pragma unroll
    for (int e = 0; e < NE; ++e) {
        if (e == i0) continue;
        float sc = p[e] + bias[e];
        if (sc > b1) { b1 = sc; i1 = e; }
    }
    float w0 = p[i0], w1 = p[i1];
    float s2 = fmaxf(w0 + w1, 1e-12f);
    w0 /= s2; w1 /= s2;

    if (lane < NE) logits_out[(size_t)t * NE + lane] = logit[lane];
    if (lane == 0) {
        d_sel[t][0] = i0; d_sel[t][1] = i1;
        d_wts[t][0] = w0; d_wts[t][1] = w1;
        d_modal[t] = mod;
    }
}

// ---------------- deterministic list build ----------------
__global__ __launch_bounds__(1024) void k_build() {
    int w = threadIdx.x >> 5, lane = threadIdx.x & 31;
    int mod = w >> 4, e = w & 15;
    int cnt = 0;
    for (int base = 0; base < T; base += 32) {
        int t = base + lane;
        int match = 0, slot = 0;
        if (d_modal[t] == mod) {
            if (d_sel[t][0] == e) { match = 1; slot = 0; }
            else if (d_sel[t][1] == e) { match = 1; slot = 1; }
        }
        unsigned m = __ballot_sync(0xffffffffu, match);
        if (match) {
            int pos = cnt + __popc(m & ((1u << lane) - 1u));
            d_pairs[mod][e][pos] = (t << 1) | slot;
        }
        cnt += __popc(m);
    }
    if (lane == 0) d_cnt[mod][e] = cnt;
}

// ---------------- prep ----------------
__global__ __launch_bounds__(256) void k_prep(
    const float* __restrict__ x, const float* __restrict__ sg,
    const float* __restrict__ su, const float* __restrict__ sd)
{
    int z = blockIdx.z;
    int tx = threadIdx.x, ty = threadIdx.y;   // 32 x 8
    int bx = blockIdx.x, by = blockIdx.y;
    if (z == 0) {
#pragma unroll
        for (int i = 0; i < 4; ++i) {
            int r = by * 32 + ty + 8 * i;
            int c = bx * 32 + tx;
            d_xt[(size_t)r * H + c] = f2tf(x[(size_t)r * H + c]);
        }
        return;
    }
    const float* src = (z == 1) ? sg : (z == 2) ? su : sd;
    uint32_t* dst = (z == 1) ? d_sgt : (z == 2) ? d_sut : d_sdt;
    __shared__ uint32_t s[32][33];
#pragma unroll
    for (int i = 0; i < 4; ++i) {
        int k = by * 32 + ty + 8 * i;
        int n = bx * 32 + tx;
        s[ty + 8 * i][tx] = f2tf(src[(size_t)k * H + n]);
    }
    __syncthreads();
#pragma unroll
    for (int i = 0; i < 4; ++i) {
        int n = bx * 32 + ty + 8 * i;
        int k = by * 32 + tx;
        dst[(size_t)n * H + k] = s[tx][ty + 8 * i];
    }
}

// ============ dense tf32 core: 128x128 tile, 256 thr, cp.async 5-stage ============
#define DSTAGES 5
__device__ __forceinline__ void dense_core(
    const uint32_t* __restrict__ A, const uint32_t* __restrict__ B,
    float* __restrict__ C, int mbase, int nbase)
{
    extern __shared__ uint32_t dsm[];
    uint32_t* sA = dsm;
    uint32_t* sB = dsm + DSTAGES * 2048;

    const int tid = threadIdx.x;
    const int lane = tid & 31;
    const int warp = tid >> 5;
    const int wm = warp & 3, wn = warp >> 2;
    const int g = lane >> 2, tg = lane & 3;

    const uint32_t saBase = (uint32_t)__cvta_generic_to_shared(sA);
    const uint32_t sbBase = (uint32_t)__cvta_generic_to_shared(sB);

    const int r0 = tid >> 2, kc0 = tid & 3;
    const int r1 = (tid + 256) >> 2, kc1 = (tid + 256) & 3;

    auto ISSUE = [&](int s, int kt) {
        {
            const uint32_t* srcA = A + (size_t)(mbase + r0) * H + kt * 16 + kc0 * 4;
            CP16(saBase + (s * 2048 + r0 * 16 + kc0 * 4) * 4, srcA);
            const uint32_t* srcB = B + (size_t)(nbase + r0) * H + kt * 16 + kc0 * 4;
            CP16(sbBase + (s * 2048 + r0 * 16 + kc0 * 4) * 4, srcB);
        }
        {
            const uint32_t* srcA = A + (size_t)(mbase + r1) * H + kt * 16 + kc1 * 4;
            CP16(saBase + (s * 2048 + r1 * 16 + kc1 * 4) * 4, srcA);
            const uint32_t* srcB = B + (size_t)(nbase + r1) * H + kt * 16 + kc1 * 4;
            CP16(sbBase + (s * 2048 + r1 * 16 + kc1 * 4) * 4, srcB);
        }
    };

    float acc[2][8][4];
#pragma unroll
    for (int a = 0; a < 2; ++a)
#pragma unroll
        for (int b = 0; b < 8; ++b)
#pragma unroll
            for (int c = 0; c < 4; ++c) acc[a][b][c] = 0.f;

    auto COMPUTE = [&](int s) {
        uint32_t Af[2][2][4];
#pragma unroll
        for (int fm = 0; fm < 2; ++fm)
#pragma unroll
            for (int rr = 0; rr < 2; ++rr) {
                int m = wm * 32 + fm * 16 + g + rr * 8;
                uint4 v = *(const uint4*)&sA[s * 2048 + m * 16 + 4 * tg];
                Af[fm][rr][0] = v.x; Af[fm][rr][1] = v.y;
                Af[fm][rr][2] = v.z; Af[fm][rr][3] = v.w;
            }
#pragma unroll
        for (int half = 0; half < 2; ++half) {
            uint32_t Bf[4][4];
#pragma unroll
            for (int f4 = 0; f4 < 4; ++f4) {
                int fn = half * 4 + f4;
                int n = wn * 64 + fn * 8 + g;
                uint4 v = *(const uint4*)&sB[s * 2048 + n * 16 + 4 * tg];
                Bf[f4][0] = v.x; Bf[f4][1] = v.y; Bf[f4][2] = v.z; Bf[f4][3] = v.w;
            }
#pragma unroll
            for (int kk = 0; kk < 2; ++kk) {
                uint32_t a[2][4];
#pragma unroll
                for (int fm = 0; fm < 2; ++fm) {
                    a[fm][0] = Af[fm][0][2 * kk];
                    a[fm][1] = Af[fm][1][2 * kk];
                    a[fm][2] = Af[fm][0][2 * kk + 1];
                    a[fm][3] = Af[fm][1][2 * kk + 1];
                }
#pragma unroll
                for (int f4 = 0; f4 < 4; ++f4) {
                    int fn = half * 4 + f4;
                    uint32_t b0 = Bf[f4][2 * kk], b1 = Bf[f4][2 * kk + 1];
                    mma_tf32(acc[0][fn], a[0], b0, b1);
                    mma_tf32(acc[1][fn], a[1], b0, b1);
                }
            }
        }
    };

    const int nk = H / 16;   // 64
#pragma unroll
    for (int p = 0; p < 4; ++p) { ISSUE(p, p); CP_COMMIT(); }
    int s = 0;
    for (int kt = 0; kt < nk; ++kt) {
        CP_WAIT3();
        __syncthreads();
        COMPUTE(s);
        if (kt + 4 < nk) {
            int s4 = s + 4; if (s4 >= DSTAGES) s4 -= DSTAGES;
            ISSUE(s4, kt + 4);
        }
        CP_COMMIT();
        if (++s == DSTAGES) s = 0;
    }

#pragma unroll
    for (int fm = 0; fm < 2; ++fm) {
#pragma unroll
        for (int h = 0; h < 2; ++h) {
            int ml = wm * 32 + fm * 16 + g + h * 8;
            int crow = mbase + ml;
#pragma unroll
            for (int fn = 0; fn < 8; ++fn) {
                int nc = nbase + wn * 64 + fn * 8 + 2 * tg;
                *(float2*)&C[(size_t)crow * H + nc] =
                    make_float2(acc[fm][fn][2 * h], acc[fm][fn][2 * h + 1]);
            }
        }
    }
}

__global__ __launch_bounds__(256) void k_shared1() {
    const uint32_t* Bm = blockIdx.z ? d_sut : d_sgt;
    float* Cm = blockIdx.z ? d_U : d_G;
    dense_core(d_xt, Bm, Cm, blockIdx.x * 128, blockIdx.y * 128);
}

__global__ __launch_bounds__(256) void k_shared2(float* __restrict__ out) {
    dense_core((const uint32_t*)d_G, d_sdt, out, blockIdx.x * 128, blockIdx.y * 128);
}

// ============ expert tf32 core: 64x128, BK=16, 4 warps, K-split via kbase ============
__device__ __forceinline__ void gemm_expert(
    int gmode,
    const float* __restrict__ A, int lda,
    const float* __restrict__ B, int ldb,
    float* __restrict__ C, int ldc,
    int K, int kbase, int mbase, int nbase,
    const int* __restrict__ plist, int cnt)
{
    __shared__ uint32_t As[2][64][16];
    __shared__ uint32_t Bs[2][128][16];
    __shared__ int rowid[64];

    const int tid = threadIdx.x;
    const int lane = tid & 31;
    const int warp = tid >> 5;
    const int wm = warp & 1, wn = warp >> 1;
    const int g = lane >> 2, tg = lane & 3;

    if (tid < 64) {
        int m = mbase + tid;
        rowid[tid] = (m < cnt) ? plist[m] : -1;
    }
    __syncthreads();

    const float* aptr[2];
    int am[2], akq[2];
#pragma unroll
    for (int j = 0; j < 2; ++j) {
        int f = tid + 128 * j;
        int m = f >> 2;
        int kq = f & 3;
        am[j] = m; akq[j] = kq;
        int pv = rowid[m];
        if (pv < 0) pv = 0;
        int r = (gmode == 1) ? (pv >> 1) : pv;
        aptr[j] = A + (size_t)r * lda + kbase + kq * 4;
    }
    const int kqB = warp;
    const int nl = lane;
    const float* bptr = B + (size_t)(kbase + 4 * kqB) * ldb + nbase + nl;
    const size_t ldb1 = ldb, ldb2 = 2 * (size_t)ldb, ldb3 = 3 * (size_t)ldb;

    float acc[2][8][4];
#pragma unroll
    for (int a = 0; a < 2; ++a)
#pragma unroll
        for (int b = 0; b < 8; ++b)
#pragma unroll
            for (int c = 0; c < 4; ++c) acc[a][b][c] = 0.f;

    float4 ar[2];
    float bv[4][4];

    auto LDG = [&]() {
#pragma unroll
        for (int j = 0; j < 2; ++j) ar[j] = *(const float4*)(aptr[j]);
#pragma unroll
        for (int grp = 0; grp < 4; ++grp) {
            bv[grp][0] = bptr[grp * 32];
            bv[grp][1] = bptr[ldb1 + grp * 32];
            bv[grp][2] = bptr[ldb2 + grp * 32];
            bv[grp][3] = bptr[ldb3 + grp * 32];
        }
        aptr[0] += 16; aptr[1] += 16;
        bptr += 16 * ldb1;
    };
    auto STS = [&](int buf) {
#pragma unroll
        for (int j = 0; j < 2; ++j) {
            int m = am[j];
            uint4 w;
            w.x = f2tf(ar[j].x); w.y = f2tf(ar[j].y);
            w.z = f2tf(ar[j].z); w.w = f2tf(ar[j].w);
            *(uint4*)&As[buf][m][(akq[j] ^ swz(m)) << 2] = w;
        }
#pragma unroll
        for (int grp = 0; grp < 4; ++grp) {
            int n = nl + 32 * grp;
            uint4 w;
            w.x = f2tf(bv[grp][0]); w.y = f2tf(bv[grp][1]);
            w.z = f2tf(bv[grp][2]); w.w = f2tf(bv[grp][3]);
            *(uint4*)&Bs[buf][n][(kqB ^ swz(n)) << 2] = w;
        }
    };
    auto COMPUTE = [&](int buf) {
        uint32_t Af[2][2][4];
#pragma unroll
        for (int fm = 0; fm < 2; ++fm)
#pragma unroll
            for (int rr = 0; rr < 2; ++rr) {
                int m = wm * 32 + fm * 16 + g + rr * 8;
                uint4 v = *(const uint4*)&As[buf][m][(tg ^ swz(m)) << 2];
                Af[fm][rr][0] = v.x; Af[fm][rr][1] = v.y;
                Af[fm][rr][2] = v.z; Af[fm][rr][3] = v.w;
            }
#pragma unroll
        for (int half = 0; half < 2; ++half) {
            uint32_t Bf[4][4];
#pragma unroll
            for (int f4 = 0; f4 < 4; ++f4) {
                int fn = half * 4 + f4;
                int n = wn * 64 + fn * 8 + g;
                uint4 v = *(const uint4*)&Bs[buf][n][(tg ^ swz(n)) << 2];
                Bf[f4][0] = v.x; Bf[f4][1] = v.y; Bf[f4][2] = v.z; Bf[f4][3] = v.w;
            }
#pragma unroll
            for (int kk = 0; kk < 2; ++kk) {
                uint32_t a[2][4];
#pragma unroll
                for (int fm = 0; fm < 2; ++fm) {
                    a[fm][0] = Af[fm][0][2 * kk];
                    a[fm][1] = Af[fm][1][2 * kk];
                    a[fm][2] = Af[fm][0][2 * kk + 1];
                    a[fm][3] = Af[fm][1][2 * kk + 1];
                }
#pragma unroll
                for (int f4 = 0; f4 < 4; ++f4) {
                    int fn = half * 4 + f4;
                    uint32_t b0 = Bf[f4][2 * kk], b1 = Bf[f4][2 * kk + 1];
                    mma_tf32(acc[0][fn], a[0], b0, b1);
                    mma_tf32(acc[1][fn], a[1], b0, b1);
                }
            }
        }
    };

    int nk = K >> 4;
    LDG();
    STS(0);
    __syncthreads();
    for (int kt = 0; kt < nk; ++kt) {
        int cur = kt & 1;
        if (kt + 1 < nk) LDG();
        COMPUTE(cur);
        if (kt + 1 < nk) STS(cur ^ 1);
        __syncthreads();
    }

#pragma unroll
    for (int fm = 0; fm < 2; ++fm) {
#pragma unroll
        for (int h = 0; h < 2; ++h) {
            int ml = wm * 32 + fm * 16 + g + h * 8;
            int pv = rowid[ml];
            if (pv < 0) continue;
#pragma unroll
            for (int fn = 0; fn < 8; ++fn) {
                int nc = nbase + wn * 64 + fn * 8 + 2 * tg;
                *(float2*)&C[(size_t)pv * ldc + nc] =
                    make_float2(acc[fm][fn][2 * h], acc[fm][fn][2 * h + 1]);
            }
        }
    }
}

// ---------------- expert pass 1: z = khalf(1b) | isup(1b) | mod/e(5b) ----------------
__global__ __launch_bounds__(128) void k_egemm1(
    const float* __restrict__ x, const float* __restrict__ tgu, const float* __restrict__ vgu)
{
    int z = blockIdx.z;
    int khalf = z >> 6;
    int zz = z & 63;
    int isup = (zz >= 32);
    int idx = zz & 31;
    int mod = idx >> 4, e = idx & 15;
    int cnt = d_cnt[mod][e];
    int mbase = blockIdx.x * 64;
    if (mbase >= cnt) return;
    int I = mod ? IV : IT;
    int nbase = blockIdx.y * 128;
    if (nbase >= I) return;
    const float* gup = (mod ? vgu : tgu) + (size_t)e * H * 2 * I + (isup ? I : 0);
    float* Cm = isup ? (khalf ? d_eu2 : d_eu) : (khalf ? d_eg2 : d_eg);
    gemm_expert(1, x, H, gup, 2 * I, Cm, IT, 512, khalf * 512,
                mbase, nbase, &d_pairs[mod][e][0], cnt);
}

// ---------------- silu: sums K-split halves; shared region -> tf32 bits ----------------
__global__ __launch_bounds__(256) void k_silu() {
    int gid = blockIdx.x * blockDim.x + threadIdx.x;
    const int NG = (T * H) / 4;
    if (gid < NG) {
        float4 gv = ((const float4*)d_G)[gid];
        float4 uv = ((const float4*)d_U)[gid];
        uint4 o;
        o.x = f2tf((gv.x / (1.f + __expf(-gv.x))) * uv.x);
        o.y = f2tf((gv.y / (1.f + __expf(-gv.y))) * uv.y);
        o.z = f2tf((gv.z / (1.f + __expf(-gv.z))) * uv.z);
        o.w = f2tf((gv.w / (1.f + __expf(-gv.w))) * uv.w);
        ((uint4*)d_G)[gid] = o;
    } else {
        int p = gid - NG;
        float4 g1 = ((const float4*)d_eg)[p];
        float4 g2 = ((const float4*)d_eg2)[p];
        float4 u1 = ((const float4*)d_eu)[p];
        float4 u2 = ((const float4*)d_eu2)[p];
        float gx = g1.x + g2.x, gy = g1.y + g2.y, gz = g1.z + g2.z, gw = g1.w + g2.w;
        float ux = u1.x + u2.x, uy = u1.y + u2.y, uz = u1.z + u2.z, uw = u1.w + u2.w;
        float4 o;
        o.x = (gx / (1.f + __expf(-gx))) * ux;
        o.y = (gy / (1.f + __expf(-gy))) * uy;
        o.z = (gz / (1.f + __expf(-gz))) * uz;
        o.w = (gw / (1.f + __expf(-gw))) * uw;
        ((float4*)d_act)[p] = o;
    }
}

// ---------------- expert pass 2: z = khalf(1b) | mod/e(5b) ----------------
__global__ __launch_bounds__(128) void k_egemm2(
    const float* __restrict__ tdn, const float* __restrict__ vdn)
{
    int z = blockIdx.z;
    int khalf = z >> 5;
    int idx = z & 31;
    int mod = idx >> 4, e = idx & 15;
    int cnt = d_cnt[mod][e];
    int mbase = blockIdx.x * 64;
    if (mbase >= cnt) return;
    int I = mod ? IV : IT;
    int nbase = blockIdx.y * 128;
    const float* dn = (mod ? vdn : tdn) + (size_t)e * I * H;
    int Khalf = I >> 1;
    float* Cm = khalf ? d_yp2 : d_yp;
    gemm_expert(2, d_act, IT, dn, H, Cm, H, Khalf, khalf * Khalf,
                mbase, nbase, &d_pairs[mod][e][0], cnt);
}

// ---------------- final combine: sums K-split halves ----------------
__global__ __launch_bounds__(256) void k_combine(float* __restrict__ out) {
    int gid = blockIdx.x * blockDim.x + threadIdx.x;
    int t = gid >> 8;
    int c4 = gid & 255;
    float w0 = d_wts[t][0], w1 = d_wts[t][1];
    float4 o = ((float4*)out)[gid];
    float4 a1 = ((const float4*)&d_yp[(size_t)(2 * t) * H])[c4];
    float4 a2 = ((const float4*)&d_yp2[(size_t)(2 * t) * H])[c4];
    float4 b1 = ((const float4*)&d_yp[(size_t)(2 * t + 1) * H])[c4];
    float4 b2 = ((const float4*)&d_yp2[(size_t)(2 * t + 1) * H])[c4];
    o.x += w0 * (a1.x + a2.x) + w1 * (b1.x + b2.x);
    o.y += w0 * (a1.y + a2.y) + w1 * (b1.y + b2.y);
    o.z += w0 * (a1.z + a2.z) + w1 * (b1.z + b2.z);
    o.w += w0 * (a1.w + a2.w) + w1 * (b1.w + b2.w);
    ((float4*)out)[gid] = o;
}

// ---------------- launch: two-branch fork/join graph ----------------
extern "C" void kernel_launch(void* const* d_in, const int* in_sizes, int n_in,
                              void* d_out, int out_size)
{
    const float* x   = (const float*)d_in[0];
    const int*   tt  = (const int*)d_in[1];
    const float* trw = (const float*)d_in[2];
    const float* tb  = (const float*)d_in[3];
    const float* tgu = (const float*)d_in[4];
    const float* tdn = (const float*)d_in[5];
    const float* vrw = (const float*)d_in[6];
    const float* vb  = (const float*)d_in[7];
    const float* vgu = (const float*)d_in[8];
    const float* vdn = (const float*)d_in[9];
    const float* sg  = (const float*)d_in[10];
    const float* su  = (const float*)d_in[11];
    const float* sd  = (const float*)d_in[12];

    float* out = (float*)d_out;
    float* logits = out + (size_t)T * H;

    const int DSM = DSTAGES * 2048 * 2 * 4;   // 81920 bytes

    static cudaStream_t s1 = nullptr;
    static cudaEvent_t evFork = nullptr, evSh1 = nullptr, evSilu = nullptr, evSh2 = nullptr;
    static int init_done = 0;
    if (!init_done) {
        cudaFuncSetAttribute(k_shared1, cudaFuncAttributeMaxDynamicSharedMemorySize, DSM);
        cudaFuncSetAttribute(k_shared2, cudaFuncAttributeMaxDynamicSharedMemorySize, DSM);
        cudaStreamCreateWithFlags(&s1, cudaStreamNonBlocking);
        cudaEventCreateWithFlags(&evFork, cudaEventDisableTiming);
        cudaEventCreateWithFlags(&evSh1,  cudaEventDisableTiming);
        cudaEventCreateWithFlags(&evSilu, cudaEventDisableTiming);
        cudaEventCreateWithFlags(&evSh2,  cudaEventDisableTiming);
        init_done = 1;
    }

    cudaStream_t S = 0;   // harness captures the default (legacy or per-thread) stream

    // fork s1 off S
    cudaEventRecord(evFork, S);
    cudaStreamWaitEvent(s1, evFork, 0);

    // branch A (s1): prep -> shared1
    k_prep<<<dim3(32, 32, 4), dim3(32, 8), 0, s1>>>(x, sg, su, sd);
    k_shared1<<<dim3(8, 8, 2), 256, DSM, s1>>>();
    cudaEventRecord(evSh1, s1);

    // branch B (S): router -> build -> egemm1
    k_router<<<128, 256, 0, S>>>(x, tt, trw, tb, vrw, vb, logits);
    k_build<<<1, 1024, 0, S>>>();
    k_egemm1<<<dim3(16, 8, 128), 128, 0, S>>>(x, tgu, vgu);

    // join for silu (needs d_G/d_U from A and d_eg*/d_eu* from B)
    cudaStreamWaitEvent(S, evSh1, 0);
    k_silu<<<2048, 256, 0, S>>>();
    cudaEventRecord(evSilu, S);

    // fork again: s1 runs shared2 (out base), S runs egemm2
    cudaStreamWaitEvent(s1, evSilu, 0);
    k_shared2<<<dim3(8, 8), 256, DSM, s1>>>(out);
    cudaEventRecord(evSh2, s1);

    k_egemm2<<<dim3(16, 8, 64), 128, 0, S>>>(tdn, vdn);

    // join: combine needs out (shared2) + d_yp* (egemm2)
    cudaStreamWaitEvent(S, evSh2, 0);
    k_combine<<<1024, 256, 0, S>>>(out);
}

// round 16
// speedup vs baseline: 1.3463x; 1.0351x over previous
#include <cuda_runtime.h>
#include <cstdint>

#define H 1024
#define T 1024
#define NE 16
#define IT 512
#define IV 256

// ---------------- scratch ----------------
__device__ float d_G[T * H];
__device__ float d_U[T * H];
__device__ float d_eg[2 * T * IT];
__device__ float d_eu[2 * T * IT];
__device__ float d_eg2[2 * T * IT];   // K-split partial (half 1)
__device__ float d_eu2[2 * T * IT];
__device__ float d_act[2 * T * IT];
__device__ float d_yp[2 * T * H];
__device__ float d_yp2[2 * T * H];    // K-split partial (half 1)
__device__ int   d_pairs[2][NE][T];
__device__ int   d_cnt[2][NE];
__device__ float d_wts[T][2];
__device__ int   d_sel[T][2];
__device__ int   d_modal[T];
__device__ uint32_t d_xt[T * H];
__device__ uint32_t d_sgt[H * H];
__device__ uint32_t d_sut[H * H];
__device__ uint32_t d_sdt[H * H];

// ---------------- helpers ----------------
__device__ __forceinline__ uint32_t f2tf(float f) {
    uint32_t r;
    asm("cvt.rna.tf32.f32 %0, %1;" : "=r"(r) : "f"(f));
    return r;
}
__device__ __forceinline__ int swz(int r) { return (r + (r >> 2)) & 3; }

__device__ __forceinline__ void mma_tf32(float* c, const uint32_t* a, uint32_t b0, uint32_t b1) {
    asm volatile(
        "mma.sync.aligned.m16n8k8.row.col.f32.tf32.tf32.f32 "
        "{%0,%1,%2,%3}, {%4,%5,%6,%7}, {%8,%9}, {%0,%1,%2,%3};"
        : "+f"(c[0]), "+f"(c[1]), "+f"(c[2]), "+f"(c[3])
        : "r"(a[0]), "r"(a[1]), "r"(a[2]), "r"(a[3]), "r"(b0), "r"(b1));
}

#define CP16(dst32, srcp) \
    asm volatile("cp.async.cg.shared.global [%0], [%1], 16;" :: "r"(dst32), "l"(srcp))
#define CP_COMMIT() asm volatile("cp.async.commit_group;" ::: "memory")
#define CP_WAIT3()  asm volatile("cp.async.wait_group 3;" ::: "memory")

// ---------------- router ----------------
__global__ __launch_bounds__(256) void k_router(
    const float* __restrict__ x, const int* __restrict__ tt,
    const float* __restrict__ Wt, const float* __restrict__ bt,
    const float* __restrict__ Wv, const float* __restrict__ bv,
    float* __restrict__ logits_out)
{
    int lane = threadIdx.x & 31;
    int t = blockIdx.x * 8 + (threadIdx.x >> 5);
    if (t >= T) return;

    int mod = (tt[t] != 0) ? 1 : 0;
    const float* W = mod ? Wv : Wt;
    const float* bias = mod ? bv : bt;

    float4 xr[8];
#pragma unroll
    for (int j = 0; j < 8; ++j)
        xr[j] = *(const float4*)&x[(size_t)t * H + (lane + 32 * j) * 4];

    float logit[NE];
#pragma unroll
    for (int e = 0; e < NE; ++e) {
        const float* w = W + (size_t)e * H;
        float s = 0.f;
#pragma unroll
        for (int j = 0; j < 8; ++j) {
            float4 wv4 = *(const float4*)&w[(lane + 32 * j) * 4];
            s = fmaf(xr[j].x, wv4.x, s);
            s = fmaf(xr[j].y, wv4.y, s);
            s = fmaf(xr[j].z, wv4.z, s);
            s = fmaf(xr[j].w, wv4.w, s);
        }
#pragma unroll
        for (int o = 16; o; o >>= 1) s += __shfl_xor_sync(0xffffffffu, s, o);
        logit[e] = s;
    }

    float mx = logit[0];
#pragma unroll
    for (int e = 1; e < NE; ++e) mx = fmaxf(mx, logit[e]);
    float p[NE], sum = 0.f;
#pragma unroll
    for (int e = 0; e < NE; ++e) { p[e] = expf(logit[e] - mx); sum += p[e]; }
    float inv = 1.f / sum;
#pragma unroll
    for (int e = 0; e < NE; ++e) p[e] *= inv;

    int i0 = 0; float b0 = -1e30f;
#pragma unroll
    for (int e = 0; e < NE; ++e) { float sc = p[e] + bias[e]; if (sc > b0) { b0 = sc; i0 = e; } }
    int i1 = 0; float b1 = -1e30f;
#pragma unroll
    for (int e = 0; e < NE; ++e) {
        if (e == i0) continue;
        float sc = p[e] + bias[e];
        if (sc > b1) { b1 = sc; i1 = e; }
    }
    float w0 = p[i0], w1 = p[i1];
    float s2 = fmaxf(w0 + w1, 1e-12f);
    w0 /= s2; w1 /= s2;

    if (lane < NE) logits_out[(size_t)t * NE + lane] = logit[lane];
    if (lane == 0) {
        d_sel[t][0] = i0; d_sel[t][1] = i1;
        d_wts[t][0] = w0; d_wts[t][1] = w1;
        d_modal[t] = mod;
    }
}

// ---------------- deterministic list build (smem-staged) ----------------
__global__ __launch_bounds__(1024) void k_build() {
    __shared__ int s_modal[T];
    __shared__ int s_sel0[T];
    __shared__ int s_sel1[T];
    int tid = threadIdx.x;
    // coalesced staging: one load per thread per array
    s_modal[tid] = d_modal[tid];
    s_sel0[tid] = d_sel[tid][0];
    s_sel1[tid] = d_sel[tid][1];
    __syncthreads();

    int w = tid >> 5, lane = tid & 31;
    int mod = w >> 4, e = w & 15;
    int cnt = 0;
    for (int base = 0; base < T; base += 32) {
        int t = base + lane;
        int match = 0, slot = 0;
        if (s_modal[t] == mod) {
            if (s_sel0[t] == e) { match = 1; slot = 0; }
            else if (s_sel1[t] == e) { match = 1; slot = 1; }
        }
        unsigned m = __ballot_sync(0xffffffffu, match);
        if (match) {
            int pos = cnt + __popc(m & ((1u << lane) - 1u));
            d_pairs[mod][e][pos] = (t << 1) | slot;
        }
        cnt += __popc(m);
    }
    if (lane == 0) d_cnt[mod][e] = cnt;
}

// ---------------- prep ----------------
__global__ __launch_bounds__(256) void k_prep(
    const float* __restrict__ x, const float* __restrict__ sg,
    const float* __restrict__ su, const float* __restrict__ sd)
{
    int z = blockIdx.z;
    int tx = threadIdx.x, ty = threadIdx.y;   // 32 x 8
    int bx = blockIdx.x, by = blockIdx.y;
    if (z == 0) {
#pragma unroll
        for (int i = 0; i < 4; ++i) {
            int r = by * 32 + ty + 8 * i;
            int c = bx * 32 + tx;
            d_xt[(size_t)r * H + c] = f2tf(x[(size_t)r * H + c]);
        }
        return;
    }
    const float* src = (z == 1) ? sg : (z == 2) ? su : sd;
    uint32_t* dst = (z == 1) ? d_sgt : (z == 2) ? d_sut : d_sdt;
    __shared__ uint32_t s[32][33];
#pragma unroll
    for (int i = 0; i < 4; ++i) {
        int k = by * 32 + ty + 8 * i;
        int n = bx * 32 + tx;
        s[ty + 8 * i][tx] = f2tf(src[(size_t)k * H + n]);
    }
    __syncthreads();
#pragma unroll
    for (int i = 0; i < 4; ++i) {
        int n = bx * 32 + ty + 8 * i;
        int k = by * 32 + tx;
        dst[(size_t)n * H + k] = s[tx][ty + 8 * i];
    }
}

// ============ dense tf32 core: 128x128 tile, 256 thr, cp.async 5-stage ============
#define DSTAGES 5
__device__ __forceinline__ void dense_core(
    const uint32_t* __restrict__ A, const uint32_t* __restrict__ B,
    float* __restrict__ C, int mbase, int nbase)
{
    extern __shared__ uint32_t dsm[];
    uint32_t* sA = dsm;
    uint32_t* sB = dsm + DSTAGES * 2048;

    const int tid = threadIdx.x;
    const int lane = tid & 31;
    const int warp = tid >> 5;
    const int wm = warp & 3, wn = warp >> 2;
    const int g = lane >> 2, tg = lane & 3;

    const uint32_t saBase = (uint32_t)__cvta_generic_to_shared(sA);
    const uint32_t sbBase = (uint32_t)__cvta_generic_to_shared(sB);

    const int r0 = tid >> 2, kc0 = tid & 3;
    const int r1 = (tid + 256) >> 2, kc1 = (tid + 256) & 3;

    auto ISSUE = [&](int s, int kt) {
        {
            const uint32_t* srcA = A + (size_t)(mbase + r0) * H + kt * 16 + kc0 * 4;
            CP16(saBase + (s * 2048 + r0 * 16 + kc0 * 4) * 4, srcA);
            const uint32_t* srcB = B + (size_t)(nbase + r0) * H + kt * 16 + kc0 * 4;
            CP16(sbBase + (s * 2048 + r0 * 16 + kc0 * 4) * 4, srcB);
        }
        {
            const uint32_t* srcA = A + (size_t)(mbase + r1) * H + kt * 16 + kc1 * 4;
            CP16(saBase + (s * 2048 + r1 * 16 + kc1 * 4) * 4, srcA);
            const uint32_t* srcB = B + (size_t)(nbase + r1) * H + kt * 16 + kc1 * 4;
            CP16(sbBase + (s * 2048 + r1 * 16 + kc1 * 4) * 4, srcB);
        }
    };

    float acc[2][8][4];
#pragma unroll
    for (int a = 0; a < 2; ++a)
#pragma unroll
        for (int b = 0; b < 8; ++b)
#pragma unroll
            for (int c = 0; c < 4; ++c) acc[a][b][c] = 0.f;

    auto COMPUTE = [&](int s) {
        uint32_t Af[2][2][4];
#pragma unroll
        for (int fm = 0; fm < 2; ++fm)
#pragma unroll
            for (int rr = 0; rr < 2; ++rr) {
                int m = wm * 32 + fm * 16 + g + rr * 8;
                uint4 v = *(const uint4*)&sA[s * 2048 + m * 16 + 4 * tg];
                Af[fm][rr][0] = v.x; Af[fm][rr][1] = v.y;
                Af[fm][rr][2] = v.z; Af[fm][rr][3] = v.w;
            }
#pragma unroll
        for (int half = 0; half < 2; ++half) {
            uint32_t Bf[4][4];
#pragma unroll
            for (int f4 = 0; f4 < 4; ++f4) {
                int fn = half * 4 + f4;
                int n = wn * 64 + fn * 8 + g;
                uint4 v = *(const uint4*)&sB[s * 2048 + n * 16 + 4 * tg];
                Bf[f4][0] = v.x; Bf[f4][1] = v.y; Bf[f4][2] = v.z; Bf[f4][3] = v.w;
            }
#pragma unroll
            for (int kk = 0; kk < 2; ++kk) {
                uint32_t a[2][4];
#pragma unroll
                for (int fm = 0; fm < 2; ++fm) {
                    a[fm][0] = Af[fm][0][2 * kk];
                    a[fm][1] = Af[fm][1][2 * kk];
                    a[fm][2] = Af[fm][0][2 * kk + 1];
                    a[fm][3] = Af[fm][1][2 * kk + 1];
                }
#pragma unroll
                for (int f4 = 0; f4 < 4; ++f4) {
                    int fn = half * 4 + f4;
                    uint32_t b0 = Bf[f4][2 * kk], b1 = Bf[f4][2 * kk + 1];
                    mma_tf32(acc[0][fn], a[0], b0, b1);
                    mma_tf32(acc[1][fn], a[1], b0, b1);
                }
            }
        }
    };

    const int nk = H / 16;   // 64
#pragma unroll
    for (int p = 0; p < 4; ++p) { ISSUE(p, p); CP_COMMIT(); }
    int s = 0;
    for (int kt = 0; kt < nk; ++kt) {
        CP_WAIT3();
        __syncthreads();
        COMPUTE(s);
        if (kt + 4 < nk) {
            int s4 = s + 4; if (s4 >= DSTAGES) s4 -= DSTAGES;
            ISSUE(s4, kt + 4);
        }
        CP_COMMIT();
        if (++s == DSTAGES) s = 0;
    }

#pragma unroll
    for (int fm = 0; fm < 2; ++fm) {
#pragma unroll
        for (int h = 0; h < 2; ++h) {
            int ml = wm * 32 + fm * 16 + g + h * 8;
            int crow = mbase + ml;
#pragma unroll
            for (int fn = 0; fn < 8; ++fn) {
                int nc = nbase + wn * 64 + fn * 8 + 2 * tg;
                *(float2*)&C[(size_t)crow * H + nc] =
                    make_float2(acc[fm][fn][2 * h], acc[fm][fn][2 * h + 1]);
            }
        }
    }
}

__global__ __launch_bounds__(256) void k_shared1() {
    const uint32_t* Bm = blockIdx.z ? d_sut : d_sgt;
    float* Cm = blockIdx.z ? d_U : d_G;
    dense_core(d_xt, Bm, Cm, blockIdx.x * 128, blockIdx.y * 128);
}

__global__ __launch_bounds__(256) void k_shared2(float* __restrict__ out) {
    dense_core((const uint32_t*)d_G, d_sdt, out, blockIdx.x * 128, blockIdx.y * 128);
}

// ============ expert tf32 core: 64x128, BK=16, 4 warps, K-split via kbase ============
__device__ __forceinline__ void gemm_expert(
    int gmode,
    const float* __restrict__ A, int lda,
    const float* __restrict__ B, int ldb,
    float* __restrict__ C, int ldc,
    int K, int kbase, int mbase, int nbase,
    const int* __restrict__ plist, int cnt)
{
    __shared__ uint32_t As[2][64][16];
    __shared__ uint32_t Bs[2][128][16];
    __shared__ int rowid[64];

    const int tid = threadIdx.x;
    const int lane = tid & 31;
    const int warp = tid >> 5;
    const int wm = warp & 1, wn = warp >> 1;
    const int g = lane >> 2, tg = lane & 3;

    if (tid < 64) {
        int m = mbase + tid;
        rowid[tid] = (m < cnt) ? plist[m] : -1;
    }
    __syncthreads();

    const float* aptr[2];
    int am[2], akq[2];
#pragma unroll
    for (int j = 0; j < 2; ++j) {
        int f = tid + 128 * j;
        int m = f >> 2;
        int kq = f & 3;
        am[j] = m; akq[j] = kq;
        int pv = rowid[m];
        if (pv < 0) pv = 0;
        int r = (gmode == 1) ? (pv >> 1) : pv;
        aptr[j] = A + (size_t)r * lda + kbase + kq * 4;
    }
    const int kqB = warp;
    const int nl = lane;
    const float* bptr = B + (size_t)(kbase + 4 * kqB) * ldb + nbase + nl;
    const size_t ldb1 = ldb, ldb2 = 2 * (size_t)ldb, ldb3 = 3 * (size_t)ldb;

    float acc[2][8][4];
#pragma unroll
    for (int a = 0; a < 2; ++a)
#pragma unroll
        for (int b = 0; b < 8; ++b)
#pragma unroll
            for (int c = 0; c < 4; ++c) acc[a][b][c] = 0.f;

    float4 ar[2];
    float bv[4][4];

    auto LDG = [&]() {
#pragma unroll
        for (int j = 0; j < 2; ++j) ar[j] = *(const float4*)(aptr[j]);
#pragma unroll
        for (int grp = 0; grp < 4; ++grp) {
            bv[grp][0] = bptr[grp * 32];
            bv[grp][1] = bptr[ldb1 + grp * 32];
            bv[grp][2] = bptr[ldb2 + grp * 32];
            bv[grp][3] = bptr[ldb3 + grp * 32];
        }
        aptr[0] += 16; aptr[1] += 16;
        bptr += 16 * ldb1;
    };
    auto STS = [&](int buf) {
#pragma unroll
        for (int j = 0; j < 2; ++j) {
            int m = am[j];
            uint4 w;
            w.x = f2tf(ar[j].x); w.y = f2tf(ar[j].y);
            w.z = f2tf(ar[j].z); w.w = f2tf(ar[j].w);
            *(uint4*)&As[buf][m][(akq[j] ^ swz(m)) << 2] = w;
        }
#pragma unroll
        for (int grp = 0; grp < 4; ++grp) {
            int n = nl + 32 * grp;
            uint4 w;
            w.x = f2tf(bv[grp][0]); w.y = f2tf(bv[grp][1]);
            w.z = f2tf(bv[grp][2]); w.w = f2tf(bv[grp][3]);
            *(uint4*)&Bs[buf][n][(kqB ^ swz(n)) << 2] = w;
        }
    };
    auto COMPUTE = [&](int buf) {
        uint32_t Af[2][2][4];
#pragma unroll
        for (int fm = 0; fm < 2; ++fm)
#pragma unroll
            for (int rr = 0; rr < 2; ++rr) {
                int m = wm * 32 + fm * 16 + g + rr * 8;
                uint4 v = *(const uint4*)&As[buf][m][(tg ^ swz(m)) << 2];
                Af[fm][rr][0] = v.x; Af[fm][rr][1] = v.y;
                Af[fm][rr][2] = v.z; Af[fm][rr][3] = v.w;
            }
#pragma unroll
        for (int half = 0; half < 2; ++half) {
            uint32_t Bf[4][4];
#pragma unroll
            for (int f4 = 0; f4 < 4; ++f4) {
                int fn = half * 4 + f4;
                int n = wn * 64 + fn * 8 + g;
                uint4 v = *(const uint4*)&Bs[buf][n][(tg ^ swz(n)) << 2];
                Bf[f4][0] = v.x; Bf[f4][1] = v.y; Bf[f4][2] = v.z; Bf[f4][3] = v.w;
            }
#pragma unroll
            for (int kk = 0; kk < 2; ++kk) {
                uint32_t a[2][4];
#pragma unroll
                for (int fm = 0; fm < 2; ++fm) {
                    a[fm][0] = Af[fm][0][2 * kk];
                    a[fm][1] = Af[fm][1][2 * kk];
                    a[fm][2] = Af[fm][0][2 * kk + 1];
                    a[fm][3] = Af[fm][1][2 * kk + 1];
                }
#pragma unroll
                for (int f4 = 0; f4 < 4; ++f4) {
                    int fn = half * 4 + f4;
                    uint32_t b0 = Bf[f4][2 * kk], b1 = Bf[f4][2 * kk + 1];
                    mma_tf32(acc[0][fn], a[0], b0, b1);
                    mma_tf32(acc[1][fn], a[1], b0, b1);
                }
            }
        }
    };

    int nk = K >> 4;
    LDG();
    STS(0);
    __syncthreads();
    for (int kt = 0; kt < nk; ++kt) {
        int cur = kt & 1;
        if (kt + 1 < nk) LDG();
        COMPUTE(cur);
        if (kt + 1 < nk) STS(cur ^ 1);
        __syncthreads();
    }

#pragma unroll
    for (int fm = 0; fm < 2; ++fm) {
#pragma unroll
        for (int h = 0; h < 2; ++h) {
            int ml = wm * 32 + fm * 16 + g + h * 8;
            int pv = rowid[ml];
            if (pv < 0) continue;
#pragma unroll
            for (int fn = 0; fn < 8; ++fn) {
                int nc = nbase + wn * 64 + fn * 8 + 2 * tg;
                *(float2*)&C[(size_t)pv * ldc + nc] =
                    make_float2(acc[fm][fn][2 * h], acc[fm][fn][2 * h + 1]);
            }
        }
    }
}

// ---------------- expert pass 1: z = khalf(1b) | isup(1b) | mod/e(5b) ----------------
__global__ __launch_bounds__(128) void k_egemm1(
    const float* __restrict__ x, const float* __restrict__ tgu, const float* __restrict__ vgu)
{
    int z = blockIdx.z;
    int khalf = z >> 6;
    int zz = z & 63;
    int isup = (zz >= 32);
    int idx = zz & 31;
    int mod = idx >> 4, e = idx & 15;
    int cnt = d_cnt[mod][e];
    int mbase = blockIdx.x * 64;
    if (mbase >= cnt) return;
    int I = mod ? IV : IT;
    int nbase = blockIdx.y * 128;
    if (nbase >= I) return;
    const float* gup = (mod ? vgu : tgu) + (size_t)e * H * 2 * I + (isup ? I : 0);
    float* Cm = isup ? (khalf ? d_eu2 : d_eu) : (khalf ? d_eg2 : d_eg);
    gemm_expert(1, x, H, gup, 2 * I, Cm, IT, 512, khalf * 512,
                mbase, nbase, &d_pairs[mod][e][0], cnt);
}

// ---------------- silu: sums K-split halves; shared region -> tf32 bits ----------------
__global__ __launch_bounds__(256) void k_silu() {
    int gid = blockIdx.x * blockDim.x + threadIdx.x;
    const int NG = (T * H) / 4;
    if (gid < NG) {
        float4 gv = ((const float4*)d_G)[gid];
        float4 uv = ((const float4*)d_U)[gid];
        uint4 o;
        o.x = f2tf((gv.x / (1.f + __expf(-gv.x))) * uv.x);
        o.y = f2tf((gv.y / (1.f + __expf(-gv.y))) * uv.y);
        o.z = f2tf((gv.z / (1.f + __expf(-gv.z))) * uv.z);
        o.w = f2tf((gv.w / (1.f + __expf(-gv.w))) * uv.w);
        ((uint4*)d_G)[gid] = o;
    } else {
        int p = gid - NG;
        float4 g1 = ((const float4*)d_eg)[p];
        float4 g2 = ((const float4*)d_eg2)[p];
        float4 u1 = ((const float4*)d_eu)[p];
        float4 u2 = ((const float4*)d_eu2)[p];
        float gx = g1.x + g2.x, gy = g1.y + g2.y, gz = g1.z + g2.z, gw = g1.w + g2.w;
        float ux = u1.x + u2.x, uy = u1.y + u2.y, uz = u1.z + u2.z, uw = u1.w + u2.w;
        float4 o;
        o.x = (gx / (1.f + __expf(-gx))) * ux;
        o.y = (gy / (1.f + __expf(-gy))) * uy;
        o.z = (gz / (1.f + __expf(-gz))) * uz;
        o.w = (gw / (1.f + __expf(-gw))) * uw;
        ((float4*)d_act)[p] = o;
    }
}

// ---------------- expert pass 2: z = khalf(1b) | mod/e(5b) ----------------
__global__ __launch_bounds__(128) void k_egemm2(
    const float* __restrict__ tdn, const float* __restrict__ vdn)
{
    int z = blockIdx.z;
    int khalf = z >> 5;
    int idx = z & 31;
    int mod = idx >> 4, e = idx & 15;
    int cnt = d_cnt[mod][e];
    int mbase = blockIdx.x * 64;
    if (mbase >= cnt) return;
    int I = mod ? IV : IT;
    int nbase = blockIdx.y * 128;
    const float* dn = (mod ? vdn : tdn) + (size_t)e * I * H;
    int Khalf = I >> 1;
    float* Cm = khalf ? d_yp2 : d_yp;
    gemm_expert(2, d_act, IT, dn, H, Cm, H, Khalf, khalf * Khalf,
                mbase, nbase, &d_pairs[mod][e][0], cnt);
}

// ---------------- final combine: sums K-split halves ----------------
__global__ __launch_bounds__(256) void k_combine(float* __restrict__ out) {
    int gid = blockIdx.x * blockDim.x + threadIdx.x;
    int t = gid >> 8;
    int c4 = gid & 255;
    float w0 = d_wts[t][0], w1 = d_wts[t][1];
    float4 o = ((float4*)out)[gid];
    float4 a1 = ((const float4*)&d_yp[(size_t)(2 * t) * H])[c4];
    float4 a2 = ((const float4*)&d_yp2[(size_t)(2 * t) * H])[c4];
    float4 b1 = ((const float4*)&d_yp[(size_t)(2 * t + 1) * H])[c4];
    float4 b2 = ((const float4*)&d_yp2[(size_t)(2 * t + 1) * H])[c4];
    o.x += w0 * (a1.x + a2.x) + w1 * (b1.x + b2.x);
    o.y += w0 * (a1.y + a2.y) + w1 * (b1.y + b2.y);
    o.z += w0 * (a1.z + a2.z) + w1 * (b1.z + b2.z);
    o.w += w0 * (a1.w + a2.w) + w1 * (b1.w + b2.w);
    ((float4*)out)[gid] = o;
}

// ---------------- launch: two-branch fork/join graph ----------------
extern "C" void kernel_launch(void* const* d_in, const int* in_sizes, int n_in,
                              void* d_out, int out_size)
{
    const float* x   = (const float*)d_in[0];
    const int*   tt  = (const int*)d_in[1];
    const float* trw = (const float*)d_in[2];
    const float* tb  = (const float*)d_in[3];
    const float* tgu = (const float*)d_in[4];
    const float* tdn = (const float*)d_in[5];
    const float* vrw = (const float*)d_in[6];
    const float* vb  = (const float*)d_in[7];
    const float* vgu = (const float*)d_in[8];
    const float* vdn = (const float*)d_in[9];
    const float* sg  = (const float*)d_in[10];
    const float* su  = (const float*)d_in[11];
    const float* sd  = (const float*)d_in[12];

    float* out = (float*)d_out;
    float* logits = out + (size_t)T * H;

    const int DSM = DSTAGES * 2048 * 2 * 4;   // 81920 bytes

    static cudaStream_t s1 = nullptr;
    static cudaEvent_t evFork = nullptr, evSh1 = nullptr, evSilu = nullptr, evSh2 = nullptr;
    static int init_done = 0;
    if (!init_done) {
        cudaFuncSetAttribute(k_shared1, cudaFuncAttributeMaxDynamicSharedMemorySize, DSM);
        cudaFuncSetAttribute(k_shared2, cudaFuncAttributeMaxDynamicSharedMemorySize, DSM);
        cudaStreamCreateWithFlags(&s1, cudaStreamNonBlocking);
        cudaEventCreateWithFlags(&evFork, cudaEventDisableTiming);
        cudaEventCreateWithFlags(&evSh1,  cudaEventDisableTiming);
        cudaEventCreateWithFlags(&evSilu, cudaEventDisableTiming);
        cudaEventCreateWithFlags(&evSh2,  cudaEventDisableTiming);
        init_done = 1;
    }

    cudaStream_t S = 0;

    // fork s1 off S
    cudaEventRecord(evFork, S);
    cudaStreamWaitEvent(s1, evFork, 0);

    // branch A (s1): prep -> shared1
    k_prep<<<dim3(32, 32, 4), dim3(32, 8), 0, s1>>>(x, sg, su, sd);
    k_shared1<<<dim3(8, 8, 2), 256, DSM, s1>>>();
    cudaEventRecord(evSh1, s1);

    // branch B (S): router -> build -> egemm1
    k_router<<<128, 256, 0, S>>>(x, tt, trw, tb, vrw, vb, logits);
    k_build<<<1, 1024, 0, S>>>();
    k_egemm1<<<dim3(16, 8, 128), 128, 0, S>>>(x, tgu, vgu);

    // join for silu (needs d_G/d_U from A and d_eg*/d_eu* from B)
    cudaStreamWaitEvent(S, evSh1, 0);
    k_silu<<<2048, 256, 0, S>>>();
    cudaEventRecord(evSilu, S);

    // fork again: s1 runs shared2 (out base), S runs egemm2
    cudaStreamWaitEvent(s1, evSilu, 0);
    k_shared2<<<dim3(8, 8), 256, DSM, s1>>>(out);
    cudaEventRecord(evSh2, s1);

    k_egemm2<<<dim3(16, 8, 64), 128, 0, S>>>(tdn, vdn);

    // join: combine needs out (shared2) + d_yp* (egemm2)
    cudaStreamWaitEvent(S, evSh2, 0);
    k_combine<<<1024, 256, 0, S>>>(out);
}

// round 17
// speedup vs baseline: 1.4228x; 1.0568x over previous
#include <cuda_runtime.h>
#include <cstdint>

#define H 1024
#define T 1024
#define NE 16
#define IT 512
#define IV 256

// ---------------- scratch ----------------
__device__ float d_G[T * H];
__device__ float d_U[T * H];
__device__ float d_eg[2 * T * IT];
__device__ float d_eu[2 * T * IT];
__device__ float d_eg2[2 * T * IT];   // K-split partial (half 1)
__device__ float d_eu2[2 * T * IT];
__device__ uint32_t d_act[2 * T * IT];   // tf32 bits (silu output)
__device__ float d_yp[2 * T * H];
__device__ float d_yp2[2 * T * H];    // K-split partial (half 1)
__device__ int   d_pairs[2][NE][T];
__device__ int   d_cnt[2][NE];
__device__ int4  d_ttab[64];          // compact tile table: (mod, e, mbase, cnt)
__device__ int   d_ntiles;
__device__ float d_wts[T][2];
__device__ int   d_sel[T][2];
__device__ int   d_modal[T];
__device__ uint32_t d_xt[T * H];
__device__ uint32_t d_sgt[H * H];
__device__ uint32_t d_sut[H * H];
__device__ uint32_t d_sdt[H * H];

// ---------------- helpers ----------------
__device__ __forceinline__ uint32_t f2tf(float f) {
    uint32_t r;
    asm("cvt.rna.tf32.f32 %0, %1;" : "=r"(r) : "f"(f));
    return r;
}
__device__ __forceinline__ int swz(int r) { return (r + (r >> 2)) & 3; }

__device__ __forceinline__ void mma_tf32(float* c, const uint32_t* a, uint32_t b0, uint32_t b1) {
    asm volatile(
        "mma.sync.aligned.m16n8k8.row.col.f32.tf32.tf32.f32 "
        "{%0,%1,%2,%3}, {%4,%5,%6,%7}, {%8,%9}, {%0,%1,%2,%3};"
        : "+f"(c[0]), "+f"(c[1]), "+f"(c[2]), "+f"(c[3])
        : "r"(a[0]), "r"(a[1]), "r"(a[2]), "r"(a[3]), "r"(b0), "r"(b1));
}

#define CP16(dst32, srcp) \
    asm volatile("cp.async.cg.shared.global [%0], [%1], 16;" :: "r"(dst32), "l"(srcp))
#define CP_COMMIT() asm volatile("cp.async.commit_group;" ::: "memory")
#define CP_WAIT3()  asm volatile("cp.async.wait_group 3;" ::: "memory")

// ---------------- router ----------------
__global__ __launch_bounds__(256) void k_router(
    const float* __restrict__ x, const int* __restrict__ tt,
    const float* __restrict__ Wt, const float* __restrict__ bt,
    const float* __restrict__ Wv, const float* __restrict__ bv,
    float* __restrict__ logits_out)
{
    int lane = threadIdx.x & 31;
    int t = blockIdx.x * 8 + (threadIdx.x >> 5);
    if (t >= T) return;

    int mod = (tt[t] != 0) ? 1 : 0;
    const float* W = mod ? Wv : Wt;
    const float* bias = mod ? bv : bt;

    float4 xr[8];
#pragma unroll
    for (int j = 0; j < 8; ++j)
        xr[j] = *(const float4*)&x[(size_t)t * H + (lane + 32 * j) * 4];

    float logit[NE];
#pragma unroll
    for (int e = 0; e < NE; ++e) {
        const float* w = W + (size_t)e * H;
        float s = 0.f;
#pragma unroll
        for (int j = 0; j < 8; ++j) {
            float4 wv4 = *(const float4*)&w[(lane + 32 * j) * 4];
            s = fmaf(xr[j].x, wv4.x, s);
            s = fmaf(xr[j].y, wv4.y, s);
            s = fmaf(xr[j].z, wv4.z, s);
            s = fmaf(xr[j].w, wv4.w, s);
        }
#pragma unroll
        for (int o = 16; o; o >>= 1) s += __shfl_xor_sync(0xffffffffu, s, o);
        logit[e] = s;
    }

    float mx = logit[0];
#pragma unroll
    for (int e = 1; e < NE; ++e) mx = fmaxf(mx, logit[e]);
    float p[NE], sum = 0.f;
#pragma unroll
    for (int e = 0; e < NE; ++e) { p[e] = expf(logit[e] - mx); sum += p[e]; }
    float inv = 1.f / sum;
#pragma unroll
    for (int e = 0; e < NE; ++e) p[e] *= inv;

    int i0 = 0; float b0 = -1e30f;
#pragma unroll
    for (int e = 0; e < NE; ++e) { float sc = p[e] + bias[e]; if (sc > b0) { b0 = sc; i0 = e; } }
    int i1 = 0; float b1 = -1e30f;
#pragma unroll
    for (int e = 0; e < NE; ++e) {
        if (e == i0) continue;
        float sc = p[e] + bias[e];
        if (sc > b1) { b1 = sc; i1 = e; }
    }
    float w0 = p[i0], w1 = p[i1];
    float s2 = fmaxf(w0 + w1, 1e-12f);
    w0 /= s2; w1 /= s2;

    if (lane < NE) logits_out[(size_t)t * NE + lane] = logit[lane];
    if (lane == 0) {
        d_sel[t][0] = i0; d_sel[t][1] = i1;
        d_wts[t][0] = w0; d_wts[t][1] = w1;
        d_modal[t] = mod;
    }
}

// ---------------- deterministic list build + compact tile table ----------------
__global__ __launch_bounds__(1024) void k_build() {
    __shared__ int s_modal[T];
    __shared__ int s_sel0[T];
    __shared__ int s_sel1[T];
    __shared__ int s_cnt[32];
    int tid = threadIdx.x;
    s_modal[tid] = d_modal[tid];
    s_sel0[tid] = d_sel[tid][0];
    s_sel1[tid] = d_sel[tid][1];
    __syncthreads();

    int w = tid >> 5, lane = tid & 31;
    int mod = w >> 4, e = w & 15;
    int cnt = 0;
    for (int base = 0; base < T; base += 32) {
        int t = base + lane;
        int match = 0, slot = 0;
        if (s_modal[t] == mod) {
            if (s_sel0[t] == e) { match = 1; slot = 0; }
            else if (s_sel1[t] == e) { match = 1; slot = 1; }
        }
        unsigned m = __ballot_sync(0xffffffffu, match);
        if (match) {
            int pos = cnt + __popc(m & ((1u << lane) - 1u));
            d_pairs[mod][e][pos] = (t << 1) | slot;
        }
        cnt += __popc(m);
    }
    if (lane == 0) { d_cnt[mod][e] = cnt; s_cnt[w] = cnt; }
    __syncthreads();
    if (tid == 0) {
        int nt = 0;
        for (int g = 0; g < 32; ++g) {
            int gm = g >> 4, ge = g & 15;
            int c = s_cnt[g];
            for (int mb = 0; mb < c; mb += 64)
                d_ttab[nt++] = make_int4(gm, ge, mb, c);
        }
        d_ntiles = nt;
    }
}

// ---------------- prep ----------------
__global__ __launch_bounds__(256) void k_prep(
    const float* __restrict__ x, const float* __restrict__ sg,
    const float* __restrict__ su, const float* __restrict__ sd)
{
    int z = blockIdx.z;
    int tx = threadIdx.x, ty = threadIdx.y;   // 32 x 8
    int bx = blockIdx.x, by = blockIdx.y;
    if (z == 0) {
#pragma unroll
        for (int i = 0; i < 4; ++i) {
            int r = by * 32 + ty + 8 * i;
            int c = bx * 32 + tx;
            d_xt[(size_t)r * H + c] = f2tf(x[(size_t)r * H + c]);
        }
        return;
    }
    const float* src = (z == 1) ? sg : (z == 2) ? su : sd;
    uint32_t* dst = (z == 1) ? d_sgt : (z == 2) ? d_sut : d_sdt;
    __shared__ uint32_t s[32][33];
#pragma unroll
    for (int i = 0; i < 4; ++i) {
        int k = by * 32 + ty + 8 * i;
        int n = bx * 32 + tx;
        s[ty + 8 * i][tx] = f2tf(src[(size_t)k * H + n]);
    }
    __syncthreads();
#pragma unroll
    for (int i = 0; i < 4; ++i) {
        int n = bx * 32 + ty + 8 * i;
        int k = by * 32 + tx;
        dst[(size_t)n * H + k] = s[tx][ty + 8 * i];
    }
}

// ============ dense tf32 core: 128x128 tile, 256 thr, cp.async 5-stage ============
#define DSTAGES 5
__device__ __forceinline__ void dense_core(
    const uint32_t* __restrict__ A, const uint32_t* __restrict__ B,
    float* __restrict__ C, int mbase, int nbase)
{
    extern __shared__ uint32_t dsm[];
    uint32_t* sA = dsm;
    uint32_t* sB = dsm + DSTAGES * 2048;

    const int tid = threadIdx.x;
    const int lane = tid & 31;
    const int warp = tid >> 5;
    const int wm = warp & 3, wn = warp >> 2;
    const int g = lane >> 2, tg = lane & 3;

    const uint32_t saBase = (uint32_t)__cvta_generic_to_shared(sA);
    const uint32_t sbBase = (uint32_t)__cvta_generic_to_shared(sB);

    const int r0 = tid >> 2, kc0 = tid & 3;
    const int r1 = (tid + 256) >> 2, kc1 = (tid + 256) & 3;

    auto ISSUE = [&](int s, int kt) {
        {
            const uint32_t* srcA = A + (size_t)(mbase + r0) * H + kt * 16 + kc0 * 4;
            CP16(saBase + (s * 2048 + r0 * 16 + kc0 * 4) * 4, srcA);
            const uint32_t* srcB = B + (size_t)(nbase + r0) * H + kt * 16 + kc0 * 4;
            CP16(sbBase + (s * 2048 + r0 * 16 + kc0 * 4) * 4, srcB);
        }
        {
            const uint32_t* srcA = A + (size_t)(mbase + r1) * H + kt * 16 + kc1 * 4;
            CP16(saBase + (s * 2048 + r1 * 16 + kc1 * 4) * 4, srcA);
            const uint32_t* srcB = B + (size_t)(nbase + r1) * H + kt * 16 + kc1 * 4;
            CP16(sbBase + (s * 2048 + r1 * 16 + kc1 * 4) * 4, srcB);
        }
    };

    float acc[2][8][4];
#pragma unroll
    for (int a = 0; a < 2; ++a)
#pragma unroll
        for (int b = 0; b < 8; ++b)
#pragma unroll
            for (int c = 0; c < 4; ++c) acc[a][b][c] = 0.f;

    auto COMPUTE = [&](int s) {
        uint32_t Af[2][2][4];
#pragma unroll
        for (int fm = 0; fm < 2; ++fm)
#pragma unroll
            for (int rr = 0; rr < 2; ++rr) {
                int m = wm * 32 + fm * 16 + g + rr * 8;
                uint4 v = *(const uint4*)&sA[s * 2048 + m * 16 + 4 * tg];
                Af[fm][rr][0] = v.x; Af[fm][rr][1] = v.y;
                Af[fm][rr][2] = v.z; Af[fm][rr][3] = v.w;
            }
#pragma unroll
        for (int half = 0; half < 2; ++half) {
            uint32_t Bf[4][4];
#pragma unroll
            for (int f4 = 0; f4 < 4; ++f4) {
                int fn = half * 4 + f4;
                int n = wn * 64 + fn * 8 + g;
                uint4 v = *(const uint4*)&sB[s * 2048 + n * 16 + 4 * tg];
                Bf[f4][0] = v.x; Bf[f4][1] = v.y; Bf[f4][2] = v.z; Bf[f4][3] = v.w;
            }
#pragma unroll
            for (int kk = 0; kk < 2; ++kk) {
                uint32_t a[2][4];
#pragma unroll
                for (int fm = 0; fm < 2; ++fm) {
                    a[fm][0] = Af[fm][0][2 * kk];
                    a[fm][1] = Af[fm][1][2 * kk];
                    a[fm][2] = Af[fm][0][2 * kk + 1];
                    a[fm][3] = Af[fm][1][2 * kk + 1];
                }
#pragma unroll
                for (int f4 = 0; f4 < 4; ++f4) {
                    int fn = half * 4 + f4;
                    uint32_t b0 = Bf[f4][2 * kk], b1 = Bf[f4][2 * kk + 1];
                    mma_tf32(acc[0][fn], a[0], b0, b1);
                    mma_tf32(acc[1][fn], a[1], b0, b1);
                }
            }
        }
    };

    const int nk = H / 16;   // 64
#pragma unroll
    for (int p = 0; p < 4; ++p) { ISSUE(p, p); CP_COMMIT(); }
    int s = 0;
    for (int kt = 0; kt < nk; ++kt) {
        CP_WAIT3();
        __syncthreads();
        COMPUTE(s);
        if (kt + 4 < nk) {
            int s4 = s + 4; if (s4 >= DSTAGES) s4 -= DSTAGES;
            ISSUE(s4, kt + 4);
        }
        CP_COMMIT();
        if (++s == DSTAGES) s = 0;
    }

#pragma unroll
    for (int fm = 0; fm < 2; ++fm) {
#pragma unroll
        for (int h = 0; h < 2; ++h) {
            int ml = wm * 32 + fm * 16 + g + h * 8;
            int crow = mbase + ml;
#pragma unroll
            for (int fn = 0; fn < 8; ++fn) {
                int nc = nbase + wn * 64 + fn * 8 + 2 * tg;
                *(float2*)&C[(size_t)crow * H + nc] =
                    make_float2(acc[fm][fn][2 * h], acc[fm][fn][2 * h + 1]);
            }
        }
    }
}

__global__ __launch_bounds__(256) void k_shared1() {
    const uint32_t* Bm = blockIdx.z ? d_sut : d_sgt;
    float* Cm = blockIdx.z ? d_U : d_G;
    dense_core(d_xt, Bm, Cm, blockIdx.x * 128, blockIdx.y * 128);
}

__global__ __launch_bounds__(256) void k_shared2(float* __restrict__ out) {
    dense_core((const uint32_t*)d_G, d_sdt, out, blockIdx.x * 128, blockIdx.y * 128);
}

// ============ expert tf32 core: 64x128, BK=16, 4 warps ============
// A is PRE-CONVERTED tf32 bits (no cvt on A path). B is fp32 (cvt at STS).
// gmode: 1 A row = pair>>1, C row = pair; 2 A row = C row = pair
__device__ __forceinline__ void gemm_expert(
    int gmode,
    const uint32_t* __restrict__ A, int lda,
    const float* __restrict__ B, int ldb,
    float* __restrict__ C, int ldc,
    int K, int kbase, int mbase, int nbase,
    const int* __restrict__ plist, int cnt)
{
    __shared__ uint32_t As[2][64][16];
    __shared__ uint32_t Bs[2][128][16];
    __shared__ int rowid[64];

    const int tid = threadIdx.x;
    const int lane = tid & 31;
    const int warp = tid >> 5;
    const int wm = warp & 1, wn = warp >> 1;
    const int g = lane >> 2, tg = lane & 3;

    if (tid < 64) {
        int m = mbase + tid;
        rowid[tid] = (m < cnt) ? plist[m] : -1;
    }
    __syncthreads();

    const uint32_t* aptr[2];
    int am[2], akq[2];
#pragma unroll
    for (int j = 0; j < 2; ++j) {
        int f = tid + 128 * j;
        int m = f >> 2;
        int kq = f & 3;
        am[j] = m; akq[j] = kq;
        int pv = rowid[m];
        if (pv < 0) pv = 0;
        int r = (gmode == 1) ? (pv >> 1) : pv;
        aptr[j] = A + (size_t)r * lda + kbase + kq * 4;
    }
    const int kqB = warp;
    const int nl = lane;
    const float* bptr = B + (size_t)(kbase + 4 * kqB) * ldb + nbase + nl;
    const size_t ldb1 = ldb, ldb2 = 2 * (size_t)ldb, ldb3 = 3 * (size_t)ldb;

    float acc[2][8][4];
#pragma unroll
    for (int a = 0; a < 2; ++a)
#pragma unroll
        for (int b = 0; b < 8; ++b)
#pragma unroll
            for (int c = 0; c < 4; ++c) acc[a][b][c] = 0.f;

    uint4 ar[2];
    float bv[4][4];

    auto LDG = [&]() {
#pragma unroll
        for (int j = 0; j < 2; ++j) ar[j] = *(const uint4*)(aptr[j]);
#pragma unroll
        for (int grp = 0; grp < 4; ++grp) {
            bv[grp][0] = bptr[grp * 32];
            bv[grp][1] = bptr[ldb1 + grp * 32];
            bv[grp][2] = bptr[ldb2 + grp * 32];
            bv[grp][3] = bptr[ldb3 + grp * 32];
        }
        aptr[0] += 16; aptr[1] += 16;
        bptr += 16 * ldb1;
    };
    auto STS = [&](int buf) {
#pragma unroll
        for (int j = 0; j < 2; ++j) {
            int m = am[j];
            *(uint4*)&As[buf][m][(akq[j] ^ swz(m)) << 2] = ar[j];
        }
#pragma unroll
        for (int grp = 0; grp < 4; ++grp) {
            int n = nl + 32 * grp;
            uint4 w;
            w.x = f2tf(bv[grp][0]); w.y = f2tf(bv[grp][1]);
            w.z = f2tf(bv[grp][2]); w.w = f2tf(bv[grp][3]);
            *(uint4*)&Bs[buf][n][(kqB ^ swz(n)) << 2] = w;
        }
    };
    auto COMPUTE = [&](int buf) {
        uint32_t Af[2][2][4];
#pragma unroll
        for (int fm = 0; fm < 2; ++fm)
#pragma unroll
            for (int rr = 0; rr < 2; ++rr) {
                int m = wm * 32 + fm * 16 + g + rr * 8;
                uint4 v = *(const uint4*)&As[buf][m][(tg ^ swz(m)) << 2];
                Af[fm][rr][0] = v.x; Af[fm][rr][1] = v.y;
                Af[fm][rr][2] = v.z; Af[fm][rr][3] = v.w;
            }
#pragma unroll
        for (int half = 0; half < 2; ++half) {
            uint32_t Bf[4][4];
#pragma unroll
            for (int f4 = 0; f4 < 4; ++f4) {
                int fn = half * 4 + f4;
                int n = wn * 64 + fn * 8 + g;
                uint4 v = *(const uint4*)&Bs[buf][n][(tg ^ swz(n)) << 2];
                Bf[f4][0] = v.x; Bf[f4][1] = v.y; Bf[f4][2] = v.z; Bf[f4][3] = v.w;
            }
#pragma unroll
            for (int kk = 0; kk < 2; ++kk) {
                uint32_t a[2][4];
#pragma unroll
                for (int fm = 0; fm < 2; ++fm) {
                    a[fm][0] = Af[fm][0][2 * kk];
                    a[fm][1] = Af[fm][1][2 * kk];
                    a[fm][2] = Af[fm][0][2 * kk + 1];
                    a[fm][3] = Af[fm][1][2 * kk + 1];
                }
#pragma unroll
                for (int f4 = 0; f4 < 4; ++f4) {
                    int fn = half * 4 + f4;
                    uint32_t b0 = Bf[f4][2 * kk], b1 = Bf[f4][2 * kk + 1];
                    mma_tf32(acc[0][fn], a[0], b0, b1);
                    mma_tf32(acc[1][fn], a[1], b0, b1);
                }
            }
        }
    };

    int nk = K >> 4;
    LDG();
    STS(0);
    __syncthreads();
    for (int kt = 0; kt < nk; ++kt) {
        int cur = kt & 1;
        if (kt + 1 < nk) LDG();
        COMPUTE(cur);
        if (kt + 1 < nk) STS(cur ^ 1);
        __syncthreads();
    }

#pragma unroll
    for (int fm = 0; fm < 2; ++fm) {
#pragma unroll
        for (int h = 0; h < 2; ++h) {
            int ml = wm * 32 + fm * 16 + g + h * 8;
            int pv = rowid[ml];
            if (pv < 0) continue;
#pragma unroll
            for (int fn = 0; fn < 8; ++fn) {
                int nc = nbase + wn * 64 + fn * 8 + 2 * tg;
                *(float2*)&C[(size_t)pv * ldc + nc] =
                    make_float2(acc[fm][fn][2 * h], acc[fm][fn][2 * h + 1]);
            }
        }
    }
}

// ---------------- expert pass 1: compact tiles; z = khalf(1b)<<1 | isup(1b) ----------------
__global__ __launch_bounds__(128) void k_egemm1(
    const float* __restrict__ tgu, const float* __restrict__ vgu)
{
    int ti = blockIdx.x;
    if (ti >= d_ntiles) return;
    int4 tt = d_ttab[ti];
    int mod = tt.x, e = tt.y, mbase = tt.z, cnt = tt.w;
    int I = mod ? IV : IT;
    int nbase = blockIdx.y * 128;
    if (nbase >= I) return;
    int z = blockIdx.z;
    int isup = z & 1, khalf = z >> 1;
    const float* gup = (mod ? vgu : tgu) + (size_t)e * H * 2 * I + (isup ? I : 0);
    float* Cm = isup ? (khalf ? d_eu2 : d_eu) : (khalf ? d_eg2 : d_eg);
    gemm_expert(1, d_xt, H, gup, 2 * I, Cm, IT, 512, khalf * 512,
                mbase, nbase, &d_pairs[mod][e][0], cnt);
}

// ---------------- silu: sums K-split halves; both regions -> tf32 bits ----------------
__global__ __launch_bounds__(256) void k_silu() {
    int gid = blockIdx.x * blockDim.x + threadIdx.x;
    const int NG = (T * H) / 4;
    if (gid < NG) {
        float4 gv = ((const float4*)d_G)[gid];
        float4 uv = ((const float4*)d_U)[gid];
        uint4 o;
        o.x = f2tf((gv.x / (1.f + __expf(-gv.x))) * uv.x);
        o.y = f2tf((gv.y / (1.f + __expf(-gv.y))) * uv.y);
        o.z = f2tf((gv.z / (1.f + __expf(-gv.z))) * uv.z);
        o.w = f2tf((gv.w / (1.f + __expf(-gv.w))) * uv.w);
        ((uint4*)d_G)[gid] = o;
    } else {
        int p = gid - NG;
        float4 g1 = ((const float4*)d_eg)[p];
        float4 g2 = ((const float4*)d_eg2)[p];
        float4 u1 = ((const float4*)d_eu)[p];
        float4 u2 = ((const float4*)d_eu2)[p];
        float gx = g1.x + g2.x, gy = g1.y + g2.y, gz = g1.z + g2.z, gw = g1.w + g2.w;
        float ux = u1.x + u2.x, uy = u1.y + u2.y, uz = u1.z + u2.z, uw = u1.w + u2.w;
        uint4 o;
        o.x = f2tf((gx / (1.f + __expf(-gx))) * ux);
        o.y = f2tf((gy / (1.f + __expf(-gy))) * uy);
        o.z = f2tf((gz / (1.f + __expf(-gz))) * uz);
        o.w = f2tf((gw / (1.f + __expf(-gw))) * uw);
        ((uint4*)d_act)[p] = o;
    }
}

// ---------------- expert pass 2: compact tiles; z = khalf ----------------
__global__ __launch_bounds__(128) void k_egemm2(
    const float* __restrict__ tdn, const float* __restrict__ vdn)
{
    int ti = blockIdx.x;
    if (ti >= d_ntiles) return;
    int4 tt = d_ttab[ti];
    int mod = tt.x, e = tt.y, mbase = tt.z, cnt = tt.w;
    int I = mod ? IV : IT;
    int nbase = blockIdx.y * 128;
    int khalf = blockIdx.z;
    const float* dn = (mod ? vdn : tdn) + (size_t)e * I * H;
    int Khalf = I >> 1;
    float* Cm = khalf ? d_yp2 : d_yp;
    gemm_expert(2, d_act, IT, dn, H, Cm, H, Khalf, khalf * Khalf,
                mbase, nbase, &d_pairs[mod][e][0], cnt);
}

// ---------------- final combine: sums K-split halves ----------------
__global__ __launch_bounds__(256) void k_combine(float* __restrict__ out) {
    int gid = blockIdx.x * blockDim.x + threadIdx.x;
    int t = gid >> 8;
    int c4 = gid & 255;
    float w0 = d_wts[t][0], w1 = d_wts[t][1];
    float4 o = ((float4*)out)[gid];
    float4 a1 = ((const float4*)&d_yp[(size_t)(2 * t) * H])[c4];
    float4 a2 = ((const float4*)&d_yp2[(size_t)(2 * t) * H])[c4];
    float4 b1 = ((const float4*)&d_yp[(size_t)(2 * t + 1) * H])[c4];
    float4 b2 = ((const float4*)&d_yp2[(size_t)(2 * t + 1) * H])[c4];
    o.x += w0 * (a1.x + a2.x) + w1 * (b1.x + b2.x);
    o.y += w0 * (a1.y + a2.y) + w1 * (b1.y + b2.y);
    o.z += w0 * (a1.z + a2.z) + w1 * (b1.z + b2.z);
    o.w += w0 * (a1.w + a2.w) + w1 * (b1.w + b2.w);
    ((float4*)out)[gid] = o;
}

// ---------------- launch: two-branch fork/join graph ----------------
extern "C" void kernel_launch(void* const* d_in, const int* in_sizes, int n_in,
                              void* d_out, int out_size)
{
    const float* x   = (const float*)d_in[0];
    const int*   tt  = (const int*)d_in[1];
    const float* trw = (const float*)d_in[2];
    const float* tb  = (const float*)d_in[3];
    const float* tgu = (const float*)d_in[4];
    const float* tdn = (const float*)d_in[5];
    const float* vrw = (const float*)d_in[6];
    const float* vb  = (const float*)d_in[7];
    const float* vgu = (const float*)d_in[8];
    const float* vdn = (const float*)d_in[9];
    const float* sg  = (const float*)d_in[10];
    const float* su  = (const float*)d_in[11];
    const float* sd  = (const float*)d_in[12];

    float* out = (float*)d_out;
    float* logits = out + (size_t)T * H;

    const int DSM = DSTAGES * 2048 * 2 * 4;   // 81920 bytes

    static cudaStream_t s1 = nullptr;
    static cudaEvent_t evFork = nullptr, evPrep = nullptr, evSh1 = nullptr,
                       evSilu = nullptr, evSh2 = nullptr;
    static int init_done = 0;
    if (!init_done) {
        cudaFuncSetAttribute(k_shared1, cudaFuncAttributeMaxDynamicSharedMemorySize, DSM);
        cudaFuncSetAttribute(k_shared2, cudaFuncAttributeMaxDynamicSharedMemorySize, DSM);
        cudaStreamCreateWithFlags(&s1, cudaStreamNonBlocking);
        cudaEventCreateWithFlags(&evFork, cudaEventDisableTiming);
        cudaEventCreateWithFlags(&evPrep, cudaEventDisableTiming);
        cudaEventCreateWithFlags(&evSh1,  cudaEventDisableTiming);
        cudaEventCreateWithFlags(&evSilu, cudaEventDisableTiming);
        cudaEventCreateWithFlags(&evSh2,  cudaEventDisableTiming);
        init_done = 1;
    }

    cudaStream_t S = 0;

    // fork s1 off S
    cudaEventRecord(evFork, S);
    cudaStreamWaitEvent(s1, evFork, 0);

    // branch A (s1): prep -> shared1
    k_prep<<<dim3(32, 32, 4), dim3(32, 8), 0, s1>>>(x, sg, su, sd);
    cudaEventRecord(evPrep, s1);             // d_xt ready (needed by egemm1 on S)
    k_shared1<<<dim3(8, 8, 2), 256, DSM, s1>>>();
    cudaEventRecord(evSh1, s1);

    // branch B (S): router -> build -> (wait prep) -> egemm1
    k_router<<<128, 256, 0, S>>>(x, tt, trw, tb, vrw, vb, logits);
    k_build<<<1, 1024, 0, S>>>();
    cudaStreamWaitEvent(S, evPrep, 0);       // egemm1 reads d_xt
    k_egemm1<<<dim3(64, 8, 4), 128, 0, S>>>(tgu, vgu);

    // join for silu (needs d_G/d_U from A and d_eg*/d_eu* from B)
    cudaStreamWaitEvent(S, evSh1, 0);
    k_silu<<<2048, 256, 0, S>>>();
    cudaEventRecord(evSilu, S);

    // fork again: s1 runs shared2 (out base), S runs egemm2
    cudaStreamWaitEvent(s1, evSilu, 0);
    k_shared2<<<dim3(8, 8), 256, DSM, s1>>>(out);
    cudaEventRecord(evSh2, s1);

    k_egemm2<<<dim3(64, 8, 2), 128, 0, S>>>(tdn, vdn);

    // join: combine needs out (shared2) + d_yp* (egemm2)
    cudaStreamWaitEvent(S, evSh2, 0);
    k_combine<<<1024, 256, 0, S>>>(out);
}